// round 2
// baseline (speedup 1.0000x reference)
#include <cuda_runtime.h>
#include <math.h>

// ---------------- problem constants ----------------
#define BSZ    8
#define CCH    3
#define IMH    384
#define IMW    384
#define PATCH  16
#define DD     768
#define NHD    12
#define HDD    64
#define MLPD   3072
#define NLAYER 12
#define NCLS   1000
#define GHH    24
#define GWW    24
#define NPATCH 576               // 24*24
#define NTOK   577               // +CLS
#define ROWS   (BSZ*NTOK)        // 4616
#define PROWS  (BSZ*NPATCH)      // 4608
#define EPSL   1e-5f
#define ATT_SCALE 0.125f         // 1/sqrt(64)

// ---------------- device scratch (no allocation allowed) ----------------
__device__ __align__(16) float g_t  [(size_t)PROWS*DD];
__device__ __align__(16) float g_emb[(size_t)PROWS*DD];
__device__ __align__(16) float g_h  [(size_t)ROWS*DD];
__device__ __align__(16) float g_y  [(size_t)ROWS*DD];
__device__ __align__(16) float g_q  [(size_t)ROWS*DD];
__device__ __align__(16) float g_k  [(size_t)ROWS*DD];
__device__ __align__(16) float g_v  [(size_t)ROWS*DD];
__device__ __align__(16) float g_ao [(size_t)ROWS*DD];
__device__ __align__(16) float g_S  [(size_t)BSZ*NHD*NTOK*NTOK];   // ~128 MB
__device__ __align__(16) float g_m  [(size_t)ROWS*MLPD];
__device__ __align__(16) float g_cls[BSZ*DD];

// ---------------- small reductions ----------------
__device__ __forceinline__ float warp_sum(float v){
    #pragma unroll
    for (int o=16;o;o>>=1) v += __shfl_xor_sync(0xffffffffu, v, o);
    return v;
}
__device__ __forceinline__ float warp_max(float v){
    #pragma unroll
    for (int o=16;o;o>>=1) v = fmaxf(v, __shfl_xor_sync(0xffffffffu, v, o));
    return v;
}

// ---------------- patch gather (faithful batch-mixing flatten) ----------------
// t linear index l = p1*(M*P) + m*P + p2, m = ((b*C+c)*GH+gh)*GW+gw
__global__ void patch_gather(const float* __restrict__ x, float* __restrict__ t){
    const int MP = BSZ*CCH*GHH*GWW*PATCH;   // 221184
    const int total = (int)((size_t)PROWS*DD);
    for (int idx = blockIdx.x*blockDim.x + threadIdx.x; idx < total;
         idx += gridDim.x*blockDim.x){
        int p1  = idx / MP;
        int rem = idx - p1*MP;
        int m   = rem >> 4;          // /PATCH
        int p2  = rem & 15;
        int gw  = m % GWW;   int m2 = m / GWW;
        int gh  = m2 % GHH;  int m3 = m2 / GHH;
        int c   = m3 % CCH;  int b  = m3 / CCH;
        t[idx] = x[(((size_t)b*CCH + c)*IMH + gh*PATCH + p1)*IMW + gw*PATCH + p2];
    }
}

// ---------------- assemble h = concat(cls, emb) + pos ----------------
__global__ void assemble(const float* __restrict__ emb, const float* __restrict__ cls,
                         const float* __restrict__ pos, float* __restrict__ h){
    const int total = (int)((size_t)ROWS*DD);
    for (int idx = blockIdx.x*blockDim.x + threadIdx.x; idx < total;
         idx += gridDim.x*blockDim.x){
        int d = idx % DD;
        int r = (idx / DD) % NTOK;
        int b = idx / (NTOK*DD);
        float v = (r==0) ? cls[d] : emb[((size_t)b*NPATCH + (r-1))*DD + d];
        h[idx] = v + pos[(size_t)r*DD + d];
    }
}

// ---------------- layernorm (one block per row) ----------------
__global__ void layernorm_k(const float* __restrict__ in, size_t ld,
                            const float* __restrict__ g, const float* __restrict__ bb,
                            float* __restrict__ out, int M){
    int row = blockIdx.x; if (row>=M) return;
    const float* xr = in + (size_t)row*ld;
    float s=0.f, ss=0.f;
    for (int i=threadIdx.x;i<DD;i+=256){ float v=xr[i]; s+=v; ss=fmaf(v,v,ss); }
    __shared__ float rs[8], rss[8];
    int lane = threadIdx.x&31, wid = threadIdx.x>>5;
    s = warp_sum(s); ss = warp_sum(ss);
    if (lane==0){ rs[wid]=s; rss[wid]=ss; }
    __syncthreads();
    if (wid==0){
        float a  = (lane<8)? rs[lane]:0.f;
        float a2 = (lane<8)? rss[lane]:0.f;
        a = warp_sum(a); a2 = warp_sum(a2);
        if (lane==0){ rs[0]=a; rss[0]=a2; }
    }
    __syncthreads();
    float mean = rs[0] * (1.f/DD);
    float var  = rss[0]*(1.f/DD) - mean*mean;
    float inv  = rsqrtf(var + EPSL);
    for (int i=threadIdx.x;i<DD;i+=256)
        out[(size_t)row*DD+i] = (xr[i]-mean)*inv*g[i] + bb[i];
}

// ---------------- generic 128x128x8 SGEMM, fused bias/GELU/residual ----------------
// C[M,Nc] = act(A[M,K] @ W[K,Nc] + bias) (+ resid)
// Global loads are vectorized (LDG.128): each thread's 4 elements are contiguous.
template<bool DOGELU, bool DORESID>
__global__ void __launch_bounds__(256)
gemm128(const float* __restrict__ A, const float* __restrict__ Wt,
        const float* __restrict__ bias, const float* __restrict__ resid,
        float* __restrict__ Cc, int M, int Nc, int K){
    __shared__ __align__(16) float As[8][132];  // transposed, padded
    __shared__ __align__(16) float Bs[8][128];
    int tid = threadIdx.x;
    int tx = tid & 15, ty = tid >> 4;
    int row0 = blockIdx.y * 128, col0 = blockIdx.x * 128;

    // A-load coords: lin = tid*4 .. tid*4+3 are 4 consecutive k-columns of one row
    const int a_r  = (tid*4) >> 3;       // 0..127
    const int a_c0 = (tid*4) & 7;        // 0 or 4
    // B-load coords: 4 consecutive output columns of one k-row
    const int b_r  = (tid*4) >> 7;       // 0..7
    const int b_c0 = (tid*4) & 127;      // multiple of 4

    float acc[8][8];
    #pragma unroll
    for (int i=0;i<8;i++)
        #pragma unroll
        for (int j=0;j<8;j++) acc[i][j]=0.f;

    for (int k0=0;k0<K;k0+=8){
        {
            int gr = row0 + a_r;
            float4 av = make_float4(0.f,0.f,0.f,0.f);
            if (gr < M) av = *(const float4*)&A[(size_t)gr*K + k0 + a_c0];
            As[a_c0+0][a_r]=av.x; As[a_c0+1][a_r]=av.y;
            As[a_c0+2][a_r]=av.z; As[a_c0+3][a_r]=av.w;
        }
        {
            int gc = col0 + b_c0;        // multiple of 4; Nc is a multiple of 4
            float4 bv = make_float4(0.f,0.f,0.f,0.f);
            if (gc < Nc) bv = *(const float4*)&Wt[(size_t)(k0+b_r)*Nc + gc];
            *(float4*)&Bs[b_r][b_c0] = bv;
        }
        __syncthreads();
        #pragma unroll
        for (int k=0;k<8;k++){
            float4 a0 = *(const float4*)&As[k][ty*8];
            float4 a1 = *(const float4*)&As[k][ty*8+4];
            float4 b0 = *(const float4*)&Bs[k][tx*8];
            float4 b1 = *(const float4*)&Bs[k][tx*8+4];
            float av[8] = {a0.x,a0.y,a0.z,a0.w,a1.x,a1.y,a1.z,a1.w};
            float bv[8] = {b0.x,b0.y,b0.z,b0.w,b1.x,b1.y,b1.z,b1.w};
            #pragma unroll
            for (int i=0;i<8;i++)
                #pragma unroll
                for (int j=0;j<8;j++)
                    acc[i][j] = fmaf(av[i], bv[j], acc[i][j]);
        }
        __syncthreads();
    }
    #pragma unroll
    for (int i=0;i<8;i++){
        int gr = row0 + ty*8 + i;
        if (gr>=M) continue;
        #pragma unroll
        for (int j=0;j<8;j++){
            int gc = col0 + tx*8 + j;
            if (gc>=Nc) continue;
            float v = acc[i][j] + bias[gc];
            if (DOGELU) v = 0.5f*v*(1.f + erff(v*0.70710678118654752f));
            if (DORESID) v += resid[(size_t)gr*Nc + gc];
            Cc[(size_t)gr*Nc + gc] = v;
        }
    }
}

// ---------------- attention: S = scale * Q @ K^T  (per batch*head) ----------------
__global__ void __launch_bounds__(256)
attn_scores(const float* __restrict__ Q, const float* __restrict__ Kk,
            float* __restrict__ S){
    int bh = blockIdx.z; int b = bh / NHD, h = bh % NHD;
    const float* qp = Q + (size_t)b*NTOK*DD + (size_t)h*HDD;
    const float* kp = Kk + (size_t)b*NTOK*DD + (size_t)h*HDD;
    float* sp = S + (size_t)bh*NTOK*NTOK;
    __shared__ float Qs[16][65], Ks[16][65];
    int tid = threadIdx.x, tx = tid & 15, ty = tid >> 4;
    int i0 = blockIdx.y*64, j0 = blockIdx.x*64;
    float acc[4][4] = {};
    for (int k0=0;k0<HDD;k0+=16){
        #pragma unroll
        for (int t=0;t<4;t++){
            int lin = tid*4+t; int r = lin>>4, c = lin&15;
            int gi = i0+r, gj = j0+r;
            Qs[c][r] = (gi<NTOK) ? qp[(size_t)gi*DD + k0 + c] : 0.f;
            Ks[c][r] = (gj<NTOK) ? kp[(size_t)gj*DD + k0 + c] : 0.f;
        }
        __syncthreads();
        #pragma unroll
        for (int k=0;k<16;k++){
            float a[4], bb[4];
            #pragma unroll
            for (int i=0;i<4;i++) a[i] = Qs[k][ty*4+i];
            #pragma unroll
            for (int j=0;j<4;j++) bb[j] = Ks[k][tx*4+j];
            #pragma unroll
            for (int i=0;i<4;i++)
                #pragma unroll
                for (int j=0;j<4;j++)
                    acc[i][j] = fmaf(a[i], bb[j], acc[i][j]);
        }
        __syncthreads();
    }
    #pragma unroll
    for (int i=0;i<4;i++){
        int gi = i0 + ty*4 + i; if (gi>=NTOK) continue;
        #pragma unroll
        for (int j=0;j<4;j++){
            int gj = j0 + tx*4 + j; if (gj>=NTOK) continue;
            sp[(size_t)gi*NTOK + gj] = acc[i][j]*ATT_SCALE;
        }
    }
}

// ---------------- softmax over last dim of S ----------------
__global__ void softmax_k(float* __restrict__ S){
    size_t row = blockIdx.x;
    float* r = S + row*NTOK;
    __shared__ float sh[8];
    int lane = threadIdx.x&31, wid = threadIdx.x>>5;
    float mx = -3.4e38f;
    for (int i=threadIdx.x;i<NTOK;i+=256) mx = fmaxf(mx, r[i]);
    mx = warp_max(mx);
    if (lane==0) sh[wid]=mx;
    __syncthreads();
    if (wid==0){
        float a = (lane<8)? sh[lane] : -3.4e38f;
        a = warp_max(a);
        if (lane==0) sh[0]=a;
    }
    __syncthreads();
    float M = sh[0];
    __syncthreads();
    float s = 0.f;
    for (int i=threadIdx.x;i<NTOK;i+=256){ float e = expf(r[i]-M); r[i]=e; s+=e; }
    s = warp_sum(s);
    if (lane==0) sh[wid]=s;
    __syncthreads();
    if (wid==0){
        float a = (lane<8)? sh[lane] : 0.f;
        a = warp_sum(a);
        if (lane==0) sh[0]=a;
    }
    __syncthreads();
    float inv = 1.f/sh[0];
    for (int i=threadIdx.x;i<NTOK;i+=256) r[i] *= inv;
}

// ---------------- attention: O = S @ V (per batch*head) ----------------
__global__ void __launch_bounds__(256)
attn_av(const float* __restrict__ S, const float* __restrict__ V,
        float* __restrict__ O){
    int bh = blockIdx.y; int b = bh / NHD, h = bh % NHD;
    const float* sp = S + (size_t)bh*NTOK*NTOK;
    const float* vp = V + (size_t)b*NTOK*DD + (size_t)h*HDD;
    float*       op = O + (size_t)b*NTOK*DD + (size_t)h*HDD;
    int i0 = blockIdx.x*64;
    __shared__ float Ss[16][65];   // Ss[k][i]
    __shared__ float Vs[16][64];   // Vs[k][d]
    int tid = threadIdx.x, tx = tid & 15, ty = tid >> 4;
    float acc[4][4] = {};
    for (int k0=0;k0<NTOK;k0+=16){
        #pragma unroll
        for (int t=0;t<4;t++){
            int lin = tid*4+t; int r = lin>>4, c = lin&15;
            int gi = i0+r, gk = k0+c;
            Ss[c][r] = (gi<NTOK && gk<NTOK) ? sp[(size_t)gi*NTOK + gk] : 0.f;
        }
        #pragma unroll
        for (int t=0;t<4;t++){
            int lin = tid*4+t; int r = lin>>6, c = lin&63;
            int gk = k0+r;
            Vs[r][c] = (gk<NTOK) ? vp[(size_t)gk*DD + c] : 0.f;
        }
        __syncthreads();
        #pragma unroll
        for (int k=0;k<16;k++){
            float a[4], bb[4];
            #pragma unroll
            for (int i=0;i<4;i++) a[i] = Ss[k][ty*4+i];
            #pragma unroll
            for (int j=0;j<4;j++) bb[j] = Vs[k][tx*4+j];
            #pragma unroll
            for (int i=0;i<4;i++)
                #pragma unroll
                for (int j=0;j<4;j++)
                    acc[i][j] = fmaf(a[i], bb[j], acc[i][j]);
        }
        __syncthreads();
    }
    #pragma unroll
    for (int i=0;i<4;i++){
        int gi = i0 + ty*4 + i; if (gi>=NTOK) continue;
        #pragma unroll
        for (int j=0;j<4;j++)
            op[(size_t)gi*DD + tx*4 + j] = acc[i][j];
    }
}

// ---------------- host driver ----------------
static inline dim3 ggrid(int M, int N){ return dim3((N+127)/128, (M+127)/128); }

extern "C" void kernel_launch(void* const* d_in, const int* in_sizes, int n_in,
                              void* d_out, int out_size){
    const float* x      = (const float*)d_in[0];
    const float* proj_w = (const float*)d_in[1];
    const float* proj_b = (const float*)d_in[2];
    const float* cls    = (const float*)d_in[3];
    const float* pos    = (const float*)d_in[4];
    const float* ln1_g  = (const float*)d_in[5];
    const float* ln1_b  = (const float*)d_in[6];
    const float* qw = (const float*)d_in[7];  const float* qb = (const float*)d_in[8];
    const float* kw = (const float*)d_in[9];  const float* kb = (const float*)d_in[10];
    const float* vw = (const float*)d_in[11]; const float* vb = (const float*)d_in[12];
    const float* ow = (const float*)d_in[13]; const float* ob = (const float*)d_in[14];
    const float* ln2_g = (const float*)d_in[15]; const float* ln2_b = (const float*)d_in[16];
    const float* fcw = (const float*)d_in[17]; const float* fcb = (const float*)d_in[18];
    const float* pw  = (const float*)d_in[19]; const float* pb  = (const float*)d_in[20];
    const float* lnf_g = (const float*)d_in[21]; const float* lnf_b = (const float*)d_in[22];
    const float* head_w = (const float*)d_in[23]; const float* head_b = (const float*)d_in[24];
    float* out = (float*)d_out;

    float *t_, *emb_, *h_, *y_, *q_, *k_, *v_, *ao_, *S_, *m_, *cls_;
    cudaGetSymbolAddress((void**)&t_,  g_t);
    cudaGetSymbolAddress((void**)&emb_,g_emb);
    cudaGetSymbolAddress((void**)&h_,  g_h);
    cudaGetSymbolAddress((void**)&y_,  g_y);
    cudaGetSymbolAddress((void**)&q_,  g_q);
    cudaGetSymbolAddress((void**)&k_,  g_k);
    cudaGetSymbolAddress((void**)&v_,  g_v);
    cudaGetSymbolAddress((void**)&ao_, g_ao);
    cudaGetSymbolAddress((void**)&S_,  g_S);
    cudaGetSymbolAddress((void**)&m_,  g_m);
    cudaGetSymbolAddress((void**)&cls_,g_cls);

    // patch embed
    patch_gather<<<2048, 256>>>(x, t_);
    gemm128<false,false><<<ggrid(PROWS, DD), 256>>>(t_, proj_w, proj_b, nullptr,
                                                    emb_, PROWS, DD, DD);
    assemble<<<2048, 256>>>(emb_, cls, pos, h_);

    dim3 gQKV = ggrid(ROWS, DD);            // (6, 37)
    dim3 gFC  = ggrid(ROWS, MLPD);          // (24, 37)
    dim3 gSc((NTOK+63)/64, (NTOK+63)/64, BSZ*NHD);   // (10,10,96)
    dim3 gAv((NTOK+63)/64, BSZ*NHD);                 // (10,96)

    for (int l=0; l<NLAYER; l++){
        const size_t wD  = (size_t)l*DD*DD;
        const size_t wF  = (size_t)l*DD*MLPD;
        layernorm_k<<<ROWS,256>>>(h_, DD, ln1_g+l*DD, ln1_b+l*DD, y_, ROWS);
        gemm128<false,false><<<gQKV,256>>>(y_, qw+wD, qb+l*DD, nullptr, q_, ROWS, DD, DD);
        gemm128<false,false><<<gQKV,256>>>(y_, kw+wD, kb+l*DD, nullptr, k_, ROWS, DD, DD);
        gemm128<false,false><<<gQKV,256>>>(y_, vw+wD, vb+l*DD, nullptr, v_, ROWS, DD, DD);
        attn_scores<<<gSc,256>>>(q_, k_, S_);
        softmax_k<<<BSZ*NHD*NTOK,256>>>(S_);
        attn_av<<<gAv,256>>>(S_, v_, ao_);
        gemm128<false,true><<<gQKV,256>>>(ao_, ow+wD, ob+l*DD, h_, h_, ROWS, DD, DD);
        layernorm_k<<<ROWS,256>>>(h_, DD, ln2_g+l*DD, ln2_b+l*DD, y_, ROWS);
        gemm128<true,false><<<gFC,256>>>(y_, fcw+wF, fcb+l*MLPD, nullptr, m_, ROWS, MLPD, DD);
        gemm128<false,true><<<gQKV,256>>>(m_, pw+wF, pb+l*DD, h_, h_, ROWS, DD, MLPD);
    }

    // final LN on CLS rows only, then head
    layernorm_k<<<BSZ,256>>>(h_, (size_t)NTOK*DD, lnf_g, lnf_b, cls_, BSZ);
    gemm128<false,false><<<ggrid(BSZ, NCLS), 256>>>(cls_, head_w, head_b, nullptr,
                                                    out, BSZ, NCLS, DD);
}

// round 9
// speedup vs baseline: 1.7873x; 1.7873x over previous
#include <cuda_runtime.h>
#include <cuda_bf16.h>
#include <math.h>
#include <stdint.h>

// ---------------- problem constants ----------------
#define BSZ    8
#define CCH    3
#define IMH    384
#define IMW    384
#define PATCH  16
#define DD     768
#define NHD    12
#define HDD    64
#define MLPD   3072
#define NLAYER 12
#define NCLS   1000
#define GHH    24
#define GWW    24
#define NPATCH 576
#define NTOK   577
#define ROWS   (BSZ*NTOK)        // 4616
#define PROWS  (BSZ*NPATCH)      // 4608
#define EPSL   1e-5f
#define ATT_SCALE 0.125f

typedef __nv_bfloat16 bf16;
typedef __nv_bfloat162 bf162;

// ---------------- device scratch (no allocation allowed) ----------------
__device__ __align__(16) float g_emb[(size_t)PROWS*DD];
__device__ __align__(16) float g_h  [(size_t)ROWS*DD];
__device__ __align__(16) float g_q  [(size_t)ROWS*DD];
__device__ __align__(16) float g_k  [(size_t)ROWS*DD];
__device__ __align__(16) float g_v  [(size_t)ROWS*DD];
__device__ __align__(16) float g_S  [(size_t)BSZ*NHD*NTOK*NTOK];
__device__ __align__(16) float g_cls[BSZ*DD];
// bf16 hi/lo activation buffers
__device__ __align__(16) bf16 g_th [(size_t)PROWS*DD];
__device__ __align__(16) bf16 g_tl [(size_t)PROWS*DD];
__device__ __align__(16) bf16 g_yh [(size_t)ROWS*DD];
__device__ __align__(16) bf16 g_yl [(size_t)ROWS*DD];
__device__ __align__(16) bf16 g_aoh[(size_t)ROWS*DD];
__device__ __align__(16) bf16 g_aol[(size_t)ROWS*DD];
__device__ __align__(16) bf16 g_mh [(size_t)ROWS*MLPD];
__device__ __align__(16) bf16 g_ml [(size_t)ROWS*MLPD];
// transposed weights [N][K] row-major, bf16 hi/lo
__device__ __align__(16) bf16 g_wqkvTh[(size_t)NLAYER*3*DD*DD];
__device__ __align__(16) bf16 g_wqkvTl[(size_t)NLAYER*3*DD*DD];
__device__ __align__(16) bf16 g_woTh  [(size_t)NLAYER*DD*DD];
__device__ __align__(16) bf16 g_woTl  [(size_t)NLAYER*DD*DD];
__device__ __align__(16) bf16 g_wfcTh [(size_t)NLAYER*MLPD*DD];
__device__ __align__(16) bf16 g_wfcTl [(size_t)NLAYER*MLPD*DD];
__device__ __align__(16) bf16 g_wpwTh [(size_t)NLAYER*DD*MLPD];
__device__ __align__(16) bf16 g_wpwTl [(size_t)NLAYER*DD*MLPD];
__device__ __align__(16) bf16 g_wprojTh[(size_t)DD*DD];
__device__ __align__(16) bf16 g_wprojTl[(size_t)DD*DD];

// ---------------- helpers ----------------
__device__ __forceinline__ void f2pair(float x, bf16& h, bf16& l){
    h = __float2bfloat16_rn(x);
    l = __float2bfloat16_rn(x - __bfloat162float(h));
}
__device__ __forceinline__ uint32_t smem_u32(const void* p){
    uint32_t a;
    asm("{ .reg .u64 t; cvta.to.shared.u64 t, %1; cvt.u32.u64 %0, t; }" : "=r"(a) : "l"(p));
    return a;
}
// ldmatrix x4 (sm_75+, OK on baseline sm_103)
__device__ __forceinline__ void ldsm4(uint32_t& r0, uint32_t& r1, uint32_t& r2, uint32_t& r3,
                                      uint32_t addr){
    asm volatile("ldmatrix.sync.aligned.m8n8.x4.shared.b16 {%0,%1,%2,%3}, [%4];"
        : "=r"(r0), "=r"(r1), "=r"(r2), "=r"(r3) : "r"(addr));
}
// mma m16n8k16 bf16 -> f32 (sm_80+, OK on baseline sm_103)
__device__ __forceinline__ void mma16816(float& d0, float& d1, float& d2, float& d3,
                                         uint32_t a0, uint32_t a1, uint32_t a2, uint32_t a3,
                                         uint32_t b0, uint32_t b1){
    asm volatile("mma.sync.aligned.m16n8k16.row.col.f32.bf16.bf16.f32 "
        "{%0,%1,%2,%3}, {%4,%5,%6,%7}, {%8,%9}, {%0,%1,%2,%3};"
        : "+f"(d0), "+f"(d1), "+f"(d2), "+f"(d3)
        : "r"(a0), "r"(a1), "r"(a2), "r"(a3), "r"(b0), "r"(b1));
}

// ---------------- small reductions ----------------
__device__ __forceinline__ float warp_sum(float v){
    #pragma unroll
    for (int o=16;o;o>>=1) v += __shfl_xor_sync(0xffffffffu, v, o);
    return v;
}
__device__ __forceinline__ float warp_max(float v){
    #pragma unroll
    for (int o=16;o;o>>=1) v = fmaxf(v, __shfl_xor_sync(0xffffffffu, v, o));
    return v;
}

// ---------------- patch gather -> bf16 hi/lo (faithful batch-mixing flatten) ----------------
__global__ void patch_gather(const float* __restrict__ x, bf16* __restrict__ th,
                             bf16* __restrict__ tl){
    const int MP = BSZ*CCH*GHH*GWW*PATCH;
    const int total = (int)((size_t)PROWS*DD);
    for (int idx = blockIdx.x*blockDim.x + threadIdx.x; idx < total;
         idx += gridDim.x*blockDim.x){
        int p1  = idx / MP;
        int rem = idx - p1*MP;
        int m   = rem >> 4;
        int p2  = rem & 15;
        int gw  = m % GWW;   int m2 = m / GWW;
        int gh  = m2 % GHH;  int m3 = m2 / GHH;
        int c   = m3 % CCH;  int b  = m3 / CCH;
        float v = x[(((size_t)b*CCH + c)*IMH + gh*PATCH + p1)*IMW + gw*PATCH + p2];
        bf16 h, l; f2pair(v, h, l);
        th[idx] = h; tl[idx] = l;
    }
}

// ---------------- assemble h = concat(cls, emb) + pos ----------------
__global__ void assemble(const float* __restrict__ emb, const float* __restrict__ cls,
                         const float* __restrict__ pos, float* __restrict__ h){
    const int total = (int)((size_t)ROWS*DD);
    for (int idx = blockIdx.x*blockDim.x + threadIdx.x; idx < total;
         idx += gridDim.x*blockDim.x){
        int d = idx % DD;
        int r = (idx / DD) % NTOK;
        int b = idx / (NTOK*DD);
        float v = (r==0) ? cls[d] : emb[((size_t)b*NPATCH + (r-1))*DD + d];
        h[idx] = v + pos[(size_t)r*DD + d];
    }
}

// ---------------- transpose fp32 [z][R][C] -> bf16 hi/lo [z][C][R] ----------------
__global__ void transpose_bf(const float* __restrict__ src, size_t sz,
                             bf16* __restrict__ dh, bf16* __restrict__ dl,
                             size_t dz, int R, int C){
    __shared__ float t[32][33];
    src += (size_t)blockIdx.z * sz;
    dh  += (size_t)blockIdx.z * dz;
    dl  += (size_t)blockIdx.z * dz;
    int c0 = blockIdx.x*32, r0 = blockIdx.y*32;
    for (int j=threadIdx.y; j<32; j+=8){
        int r=r0+j, c=c0+threadIdx.x;
        if (r<R && c<C) t[j][threadIdx.x] = src[(size_t)r*C+c];
    }
    __syncthreads();
    for (int j=threadIdx.y; j<32; j+=8){
        int c=c0+j, r=r0+threadIdx.x;
        if (r<R && c<C){
            bf16 h, l; f2pair(t[threadIdx.x][j], h, l);
            dh[(size_t)c*R+r] = h; dl[(size_t)c*R+r] = l;
        }
    }
}

// ---------------- layernorm -> bf16 hi/lo pair ----------------
__global__ void layernorm_bf(const float* __restrict__ in,
                             const float* __restrict__ g, const float* __restrict__ bb,
                             bf16* __restrict__ oh, bf16* __restrict__ ol, int M){
    int row = blockIdx.x; if (row>=M) return;
    const float4* xr = (const float4*)(in + (size_t)row*DD);
    float s=0.f, ss=0.f;
    for (int i=threadIdx.x;i<DD/4;i+=256){
        float4 v=xr[i];
        s += v.x+v.y+v.z+v.w;
        ss = fmaf(v.x,v.x,fmaf(v.y,v.y,fmaf(v.z,v.z,fmaf(v.w,v.w,ss))));
    }
    __shared__ float rs[8], rss[8];
    int lane = threadIdx.x&31, wid = threadIdx.x>>5;
    s = warp_sum(s); ss = warp_sum(ss);
    if (lane==0){ rs[wid]=s; rss[wid]=ss; }
    __syncthreads();
    if (wid==0){
        float a  = (lane<8)? rs[lane]:0.f;
        float a2 = (lane<8)? rss[lane]:0.f;
        a = warp_sum(a); a2 = warp_sum(a2);
        if (lane==0){ rs[0]=a; rss[0]=a2; }
    }
    __syncthreads();
    float mean = rs[0] * (1.f/DD);
    float var  = rss[0]*(1.f/DD) - mean*mean;
    float inv  = rsqrtf(var + EPSL);
    const float2* x2 = (const float2*)(in + (size_t)row*DD);
    const float2* g2 = (const float2*)g;
    const float2* b2 = (const float2*)bb;
    bf162* oh2 = (bf162*)(oh + (size_t)row*DD);
    bf162* ol2 = (bf162*)(ol + (size_t)row*DD);
    for (int i=threadIdx.x;i<DD/2;i+=256){
        float2 v=x2[i], gg=g2[i], bv=b2[i];
        float r0=(v.x-mean)*inv*gg.x+bv.x, r1=(v.y-mean)*inv*gg.y+bv.y;
        bf162 hv, lv;
        f2pair(r0, hv.x, lv.x); f2pair(r1, hv.y, lv.y);
        oh2[i]=hv; ol2[i]=lv;
    }
}

// ---------------- layernorm fp32 out (final LN on CLS rows) ----------------
__global__ void layernorm_f(const float* __restrict__ in, size_t ld,
                            const float* __restrict__ g, const float* __restrict__ bb,
                            float* __restrict__ out, int M){
    int row = blockIdx.x; if (row>=M) return;
    const float* xr = in + (size_t)row*ld;
    float s=0.f, ss=0.f;
    for (int i=threadIdx.x;i<DD;i+=256){ float v=xr[i]; s+=v; ss=fmaf(v,v,ss); }
    __shared__ float rs[8], rss[8];
    int lane = threadIdx.x&31, wid = threadIdx.x>>5;
    s = warp_sum(s); ss = warp_sum(ss);
    if (lane==0){ rs[wid]=s; rss[wid]=ss; }
    __syncthreads();
    if (wid==0){
        float a  = (lane<8)? rs[lane]:0.f;
        float a2 = (lane<8)? rss[lane]:0.f;
        a = warp_sum(a); a2 = warp_sum(a2);
        if (lane==0){ rs[0]=a; rss[0]=a2; }
    }
    __syncthreads();
    float mean = rs[0] * (1.f/DD);
    float var  = rss[0]*(1.f/DD) - mean*mean;
    float inv  = rsqrtf(var + EPSL);
    for (int i=threadIdx.x;i<DD;i+=256)
        out[(size_t)row*DD+i] = (xr[i]-mean)*inv*g[i] + bb[i];
}

// ======================================================================
// mma.sync split-bf16 GEMM: C = act(A @ WT^T + bias) [+resid]
// A as bf16 hi/lo [M,K]; WT as bf16 hi/lo [Nc,K] (pre-transposed).
// 128x128 CTA tile, 8 warps (2x4), 64x32 warp tile, m16n8k16 bf16 HMMA.
// 3 terms: ah*bh + ah*bl + al*bh, fp32 accumulators in registers.
// MODE: 0 = bias -> fp32 C ; 1 = bias+resid -> fp32 C ; 2 = bias+GELU -> bf16 pair
// ======================================================================
#define SKP 40   // padded row stride (bf16 elems) for conflict-free ldmatrix
template<int MODE>
__global__ void __launch_bounds__(256)
gemm_tc(const bf16* __restrict__ Ah, const bf16* __restrict__ Al,
        const bf16* __restrict__ Bh0, const bf16* __restrict__ Bl0,
        const float* __restrict__ b0, const float* __restrict__ b1, const float* __restrict__ b2,
        const float* __restrict__ resid,
        float* C0, float* C1, float* C2,
        bf16* Ch, bf16* Cl,
        int M, int Nc, int K)
{
    __shared__ __align__(16) bf16 sAh[128*SKP];
    __shared__ __align__(16) bf16 sAl[128*SKP];
    __shared__ __align__(16) bf16 sBh[128*SKP];
    __shared__ __align__(16) bf16 sBl[128*SKP];

    const int z = blockIdx.z;
    const bf16* Bh = Bh0 + (size_t)z * Nc * K;
    const bf16* Bl = Bl0 + (size_t)z * Nc * K;
    const float* bias = (z==0)?b0:((z==1)?b1:b2);
    float* C = (z==0)?C0:((z==1)?C1:C2);

    const int tid = threadIdx.x, wid = tid>>5, lane = tid&31;
    const int warp_m = wid>>2, warp_n = wid&3;       // 2 x 4
    const int row0 = blockIdx.y*128, col0 = blockIdx.x*128;

    // ---- loader mapping: thread t -> row t>>1, k-halves (t&1)*16 ----
    const int lrow = tid>>1, lk = (tid&1)*16;
    const bool aval = (row0+lrow) < M;
    const bf16* pAh = Ah + (size_t)(row0+lrow)*K + lk;
    const bf16* pAl = Al + (size_t)(row0+lrow)*K + lk;
    const bf16* pBh = Bh + (size_t)(col0+lrow)*K + lk;
    const bf16* pBl = Bl + (size_t)(col0+lrow)*K + lk;
    const int soff = lrow*SKP + lk;
    const uint4 zz = make_uint4(0,0,0,0);

    // ---- ldmatrix lane addresses ----
    // A (m16k16 x4): groups of 8 lanes -> (m+0/k+0),(m+8/k+0),(m+0/k+8),(m+8/k+8)
    const int a_m = warp_m*64 + (lane&7) + ((lane>>3)&1)*8;
    const int a_k = (lane>>4)*8;
    const uint32_t aAh = smem_u32(sAh) + (uint32_t)(a_m*SKP + a_k)*2;
    const uint32_t aAl = smem_u32(sAl) + (uint32_t)(a_m*SKP + a_k)*2;
    // B (two n-tiles per x4): groups -> (n+0/k+0),(n+0/k+8),(n+8/k+0),(n+8/k+8)
    const int b_n = warp_n*32 + (lane&7) + (lane>>4)*8;
    const int b_k = ((lane>>3)&1)*8;
    const uint32_t aBh = smem_u32(sBh) + (uint32_t)(b_n*SKP + b_k)*2;
    const uint32_t aBl = smem_u32(sBl) + (uint32_t)(b_n*SKP + b_k)*2;

    float acc[4][4][4];
    #pragma unroll
    for (int i=0;i<4;i++)
        #pragma unroll
        for (int j=0;j<4;j++)
            #pragma unroll
            for (int r=0;r<4;r++) acc[i][j][r]=0.f;

    const int NCH = K>>5;   // chunks of 32 k-elems
    uint4 ra0, ra1, rb0, rb1, rc0, rc1, rd0, rd1;

    // load chunk 0
    ra0 = aval ? *(const uint4*)(pAh)     : zz;
    ra1 = aval ? *(const uint4*)(pAh + 8) : zz;
    rb0 = aval ? *(const uint4*)(pAl)     : zz;
    rb1 = aval ? *(const uint4*)(pAl + 8) : zz;
    rc0 = *(const uint4*)(pBh);      rc1 = *(const uint4*)(pBh + 8);
    rd0 = *(const uint4*)(pBl);      rd1 = *(const uint4*)(pBl + 8);
    *(uint4*)(&sAh[soff]) = ra0; *(uint4*)(&sAh[soff+8]) = ra1;
    *(uint4*)(&sAl[soff]) = rb0; *(uint4*)(&sAl[soff+8]) = rb1;
    *(uint4*)(&sBh[soff]) = rc0; *(uint4*)(&sBh[soff+8]) = rc1;
    *(uint4*)(&sBl[soff]) = rd0; *(uint4*)(&sBl[soff+8]) = rd1;
    __syncthreads();

    for (int ch=0; ch<NCH; ch++){
        // prefetch next chunk to registers (overlaps with MMA below)
        if (ch+1 < NCH){
            int o = (ch+1)*32;
            ra0 = aval ? *(const uint4*)(pAh + o)     : zz;
            ra1 = aval ? *(const uint4*)(pAh + o + 8) : zz;
            rb0 = aval ? *(const uint4*)(pAl + o)     : zz;
            rb1 = aval ? *(const uint4*)(pAl + o + 8) : zz;
            rc0 = *(const uint4*)(pBh + o);  rc1 = *(const uint4*)(pBh + o + 8);
            rd0 = *(const uint4*)(pBl + o);  rd1 = *(const uint4*)(pBl + o + 8);
        }
        // compute: two k16 steps on current chunk
        #pragma unroll
        for (int k16=0;k16<2;k16++){
            const uint32_t ko = (uint32_t)k16*32;   // 16 elems * 2B
            uint32_t af[4][4], bh[2][4], bl[2][4];
            #pragma unroll
            for (int i=0;i<4;i++)
                ldsm4(af[i][0],af[i][1],af[i][2],af[i][3], aAh + i*16*SKP*2 + ko);
            #pragma unroll
            for (int p=0;p<2;p++)
                ldsm4(bh[p][0],bh[p][1],bh[p][2],bh[p][3], aBh + p*16*SKP*2 + ko);
            #pragma unroll
            for (int p=0;p<2;p++)
                ldsm4(bl[p][0],bl[p][1],bl[p][2],bl[p][3], aBl + p*16*SKP*2 + ko);
            // term 1: ah * bh
            #pragma unroll
            for (int i=0;i<4;i++)
                #pragma unroll
                for (int j=0;j<4;j++)
                    mma16816(acc[i][j][0],acc[i][j][1],acc[i][j][2],acc[i][j][3],
                             af[i][0],af[i][1],af[i][2],af[i][3],
                             bh[j>>1][(j&1)*2], bh[j>>1][(j&1)*2+1]);
            // term 2: ah * bl
            #pragma unroll
            for (int i=0;i<4;i++)
                #pragma unroll
                for (int j=0;j<4;j++)
                    mma16816(acc[i][j][0],acc[i][j][1],acc[i][j][2],acc[i][j][3],
                             af[i][0],af[i][1],af[i][2],af[i][3],
                             bl[j>>1][(j&1)*2], bl[j>>1][(j&1)*2+1]);
            // term 3: al * bh  (reload A frags from lo buffer)
            #pragma unroll
            for (int i=0;i<4;i++)
                ldsm4(af[i][0],af[i][1],af[i][2],af[i][3], aAl + i*16*SKP*2 + ko);
            #pragma unroll
            for (int i=0;i<4;i++)
                #pragma unroll
                for (int j=0;j<4;j++)
                    mma16816(acc[i][j][0],acc[i][j][1],acc[i][j][2],acc[i][j][3],
                             af[i][0],af[i][1],af[i][2],af[i][3],
                             bh[j>>1][(j&1)*2], bh[j>>1][(j&1)*2+1]);
        }
        __syncthreads();
        if (ch+1 < NCH){
            *(uint4*)(&sAh[soff]) = ra0; *(uint4*)(&sAh[soff+8]) = ra1;
            *(uint4*)(&sAl[soff]) = rb0; *(uint4*)(&sAl[soff+8]) = rb1;
            *(uint4*)(&sBh[soff]) = rc0; *(uint4*)(&sBh[soff+8]) = rc1;
            *(uint4*)(&sBl[soff]) = rd0; *(uint4*)(&sBl[soff+8]) = rd1;
            __syncthreads();
        }
    }

    // ---- epilogue: accumulators are in registers ----
    #pragma unroll
    for (int i=0;i<4;i++){
        #pragma unroll
        for (int j=0;j<4;j++){
            int m0 = row0 + warp_m*64 + i*16 + (lane>>2);
            int n0 = col0 + warp_n*32 + j*8 + (lane&3)*2;
            float bs0 = bias[n0], bs1 = bias[n0+1];
            #pragma unroll
            for (int half=0; half<2; half++){
                int m = m0 + half*8;
                if (m >= M) continue;
                float v0 = acc[i][j][half*2]   + bs0;
                float v1 = acc[i][j][half*2+1] + bs1;
                if (MODE == 1){
                    const float2 rv = *(const float2*)(resid + (size_t)m*Nc + n0);
                    v0 += rv.x; v1 += rv.y;
                }
                if (MODE == 2){
                    v0 = 0.5f*v0*(1.f + erff(v0*0.70710678118654752f));
                    v1 = 0.5f*v1*(1.f + erff(v1*0.70710678118654752f));
                    bf162 hv, lv;
                    f2pair(v0, hv.x, lv.x); f2pair(v1, hv.y, lv.y);
                    *(bf162*)(Ch + (size_t)m*Nc + n0) = hv;
                    *(bf162*)(Cl + (size_t)m*Nc + n0) = lv;
                } else {
                    float2 ov; ov.x=v0; ov.y=v1;
                    *(float2*)(C + (size_t)m*Nc + n0) = ov;
                }
            }
        }
    }
}

// ---------------- SIMT gemm for the tiny head GEMM ----------------
__global__ void __launch_bounds__(256)
gemm128(const float* __restrict__ A, const float* __restrict__ Wt,
        const float* __restrict__ bias, float* __restrict__ Cc,
        int M, int Nc, int K){
    __shared__ __align__(16) float As[8][132];
    __shared__ __align__(16) float Bs[8][128];
    int tid = threadIdx.x;
    int tx = tid & 15, ty = tid >> 4;
    int row0 = blockIdx.y * 128, col0 = blockIdx.x * 128;
    float acc[8][8];
    #pragma unroll
    for (int i=0;i<8;i++)
        #pragma unroll
        for (int j=0;j<8;j++) acc[i][j]=0.f;
    for (int k0=0;k0<K;k0+=8){
        #pragma unroll
        for (int t=0;t<4;t++){
            int lin = tid*4+t;
            int r = lin>>3, c = lin&7;
            int gr = row0+r;
            As[c][r] = (gr<M) ? A[(size_t)gr*K + k0 + c] : 0.f;
        }
        #pragma unroll
        for (int t=0;t<4;t++){
            int lin = tid*4+t;
            int r = lin>>7, c = lin&127;
            int gc = col0+c;
            Bs[r][c] = (gc<Nc) ? Wt[(size_t)(k0+r)*Nc + gc] : 0.f;
        }
        __syncthreads();
        #pragma unroll
        for (int k=0;k<8;k++){
            float av[8], bv[8];
            #pragma unroll
            for (int i=0;i<8;i++) av[i]=As[k][ty*8+i];
            #pragma unroll
            for (int j=0;j<8;j++) bv[j]=Bs[k][tx*8+j];
            #pragma unroll
            for (int i=0;i<8;i++)
                #pragma unroll
                for (int j=0;j<8;j++)
                    acc[i][j] = fmaf(av[i], bv[j], acc[i][j]);
        }
        __syncthreads();
    }
    #pragma unroll
    for (int i=0;i<8;i++){
        int gr = row0 + ty*8 + i;
        if (gr>=M) continue;
        #pragma unroll
        for (int j=0;j<8;j++){
            int gc = col0 + tx*8 + j;
            if (gc>=Nc) continue;
            Cc[(size_t)gr*Nc + gc] = acc[i][j] + bias[gc];
        }
    }
}

// ---------------- attention: S = scale * Q @ K^T ----------------
__global__ void __launch_bounds__(256)
attn_scores(const float* __restrict__ Q, const float* __restrict__ Kk,
            float* __restrict__ S){
    int bh = blockIdx.z; int b = bh / NHD, h = bh % NHD;
    const float* qp = Q + (size_t)b*NTOK*DD + (size_t)h*HDD;
    const float* kp = Kk + (size_t)b*NTOK*DD + (size_t)h*HDD;
    float* sp = S + (size_t)bh*NTOK*NTOK;
    __shared__ float Qs[16][65], Ks[16][65];
    int tid = threadIdx.x, tx = tid & 15, ty = tid >> 4;
    int i0 = blockIdx.y*64, j0 = blockIdx.x*64;
    float acc[4][4] = {};
    for (int k0=0;k0<HDD;k0+=16){
        #pragma unroll
        for (int t=0;t<4;t++){
            int lin = tid*4+t; int r = lin>>4, c = lin&15;
            int gi = i0+r, gj = j0+r;
            Qs[c][r] = (gi<NTOK) ? qp[(size_t)gi*DD + k0 + c] : 0.f;
            Ks[c][r] = (gj<NTOK) ? kp[(size_t)gj*DD + k0 + c] : 0.f;
        }
        __syncthreads();
        #pragma unroll
        for (int k=0;k<16;k++){
            float a[4], bb[4];
            #pragma unroll
            for (int i=0;i<4;i++) a[i] = Qs[k][ty*4+i];
            #pragma unroll
            for (int j=0;j<4;j++) bb[j] = Ks[k][tx*4+j];
            #pragma unroll
            for (int i=0;i<4;i++)
                #pragma unroll
                for (int j=0;j<4;j++)
                    acc[i][j] = fmaf(a[i], bb[j], acc[i][j]);
        }
        __syncthreads();
    }
    #pragma unroll
    for (int i=0;i<4;i++){
        int gi = i0 + ty*4 + i; if (gi>=NTOK) continue;
        #pragma unroll
        for (int j=0;j<4;j++){
            int gj = j0 + tx*4 + j; if (gj>=NTOK) continue;
            sp[(size_t)gi*NTOK + gj] = acc[i][j]*ATT_SCALE;
        }
    }
}

// ---------------- softmax ----------------
__global__ void softmax_k(float* __restrict__ S){
    size_t row = blockIdx.x;
    float* r = S + row*NTOK;
    __shared__ float sh[8];
    int lane = threadIdx.x&31, wid = threadIdx.x>>5;
    float mx = -3.4e38f;
    for (int i=threadIdx.x;i<NTOK;i+=256) mx = fmaxf(mx, r[i]);
    mx = warp_max(mx);
    if (lane==0) sh[wid]=mx;
    __syncthreads();
    if (wid==0){
        float a = (lane<8)? sh[lane] : -3.4e38f;
        a = warp_max(a);
        if (lane==0) sh[0]=a;
    }
    __syncthreads();
    float M = sh[0];
    __syncthreads();
    float s = 0.f;
    for (int i=threadIdx.x;i<NTOK;i+=256){ float e = expf(r[i]-M); r[i]=e; s+=e; }
    s = warp_sum(s);
    if (lane==0) sh[wid]=s;
    __syncthreads();
    if (wid==0){
        float a = (lane<8)? sh[lane] : 0.f;
        a = warp_sum(a);
        if (lane==0) sh[0]=a;
    }
    __syncthreads();
    float inv = 1.f/sh[0];
    for (int i=threadIdx.x;i<NTOK;i+=256) r[i] *= inv;
}

// ---------------- attention: O = S @ V -> bf16 hi/lo ----------------
__global__ void __launch_bounds__(256)
attn_av(const float* __restrict__ S, const float* __restrict__ V,
        bf16* __restrict__ Oh, bf16* __restrict__ Ol){
    int bh = blockIdx.y; int b = bh / NHD, h = bh % NHD;
    const float* sp = S + (size_t)bh*NTOK*NTOK;
    const float* vp = V + (size_t)b*NTOK*DD + (size_t)h*HDD;
    bf16* oph = Oh + (size_t)b*NTOK*DD + (size_t)h*HDD;
    bf16* opl = Ol + (size_t)b*NTOK*DD + (size_t)h*HDD;
    int i0 = blockIdx.x*64;
    __shared__ float Ss[16][65];
    __shared__ float Vs[16][64];
    int tid = threadIdx.x, tx = tid & 15, ty = tid >> 4;
    float acc[4][4] = {};
    for (int k0=0;k0<NTOK;k0+=16){
        #pragma unroll
        for (int t=0;t<4;t++){
            int lin = tid*4+t; int r = lin>>4, c = lin&15;
            int gi = i0+r, gk = k0+c;
            Ss[c][r] = (gi<NTOK && gk<NTOK) ? sp[(size_t)gi*NTOK + gk] : 0.f;
        }
        #pragma unroll
        for (int t=0;t<4;t++){
            int lin = tid*4+t; int r = lin>>6, c = lin&63;
            int gk = k0+r;
            Vs[r][c] = (gk<NTOK) ? vp[(size_t)gk*DD + c] : 0.f;
        }
        __syncthreads();
        #pragma unroll
        for (int k=0;k<16;k++){
            float a[4], bb[4];
            #pragma unroll
            for (int i=0;i<4;i++) a[i] = Ss[k][ty*4+i];
            #pragma unroll
            for (int j=0;j<4;j++) bb[j] = Vs[k][tx*4+j];
            #pragma unroll
            for (int i=0;i<4;i++)
                #pragma unroll
                for (int j=0;j<4;j++)
                    acc[i][j] = fmaf(a[i], bb[j], acc[i][j]);
        }
        __syncthreads();
    }
    #pragma unroll
    for (int i=0;i<4;i++){
        int gi = i0 + ty*4 + i; if (gi>=NTOK) continue;
        #pragma unroll
        for (int j2=0;j2<2;j2++){
            bf162 hv, lv;
            f2pair(acc[i][j2*2  ], hv.x, lv.x);
            f2pair(acc[i][j2*2+1], hv.y, lv.y);
            *(bf162*)(oph + (size_t)gi*DD + tx*4 + j2*2) = hv;
            *(bf162*)(opl + (size_t)gi*DD + tx*4 + j2*2) = lv;
        }
    }
}

// ---------------- host driver ----------------
extern "C" void kernel_launch(void* const* d_in, const int* in_sizes, int n_in,
                              void* d_out, int out_size){
    const float* x      = (const float*)d_in[0];
    const float* proj_w = (const float*)d_in[1];
    const float* proj_b = (const float*)d_in[2];
    const float* cls    = (const float*)d_in[3];
    const float* pos    = (const float*)d_in[4];
    const float* ln1_g  = (const float*)d_in[5];
    const float* ln1_b  = (const float*)d_in[6];
    const float* qw = (const float*)d_in[7];  const float* qb = (const float*)d_in[8];
    const float* kw = (const float*)d_in[9];  const float* kb = (const float*)d_in[10];
    const float* vw = (const float*)d_in[11]; const float* vb = (const float*)d_in[12];
    const float* ow = (const float*)d_in[13]; const float* ob = (const float*)d_in[14];
    const float* ln2_g = (const float*)d_in[15]; const float* ln2_b = (const float*)d_in[16];
    const float* fcw = (const float*)d_in[17]; const float* fcb = (const float*)d_in[18];
    const float* pw  = (const float*)d_in[19]; const float* pb  = (const float*)d_in[20];
    const float* lnf_g = (const float*)d_in[21]; const float* lnf_b = (const float*)d_in[22];
    const float* head_w = (const float*)d_in[23]; const float* head_b = (const float*)d_in[24];
    float* out = (float*)d_out;

    float *emb_, *h_, *q_, *k_, *v_, *S_, *cls_;
    bf16 *th_, *tl_, *yh_, *yl_, *aoh_, *aol_, *mh_, *ml_;
    bf16 *wqkvTh_, *wqkvTl_, *woTh_, *woTl_, *wfcTh_, *wfcTl_, *wpwTh_, *wpwTl_, *wprojTh_, *wprojTl_;
    cudaGetSymbolAddress((void**)&emb_,g_emb);
    cudaGetSymbolAddress((void**)&h_,  g_h);
    cudaGetSymbolAddress((void**)&q_,  g_q);
    cudaGetSymbolAddress((void**)&k_,  g_k);
    cudaGetSymbolAddress((void**)&v_,  g_v);
    cudaGetSymbolAddress((void**)&S_,  g_S);
    cudaGetSymbolAddress((void**)&cls_,g_cls);
    cudaGetSymbolAddress((void**)&th_, g_th);
    cudaGetSymbolAddress((void**)&tl_, g_tl);
    cudaGetSymbolAddress((void**)&yh_, g_yh);
    cudaGetSymbolAddress((void**)&yl_, g_yl);
    cudaGetSymbolAddress((void**)&aoh_,g_aoh);
    cudaGetSymbolAddress((void**)&aol_,g_aol);
    cudaGetSymbolAddress((void**)&mh_, g_mh);
    cudaGetSymbolAddress((void**)&ml_, g_ml);
    cudaGetSymbolAddress((void**)&wqkvTh_, g_wqkvTh);
    cudaGetSymbolAddress((void**)&wqkvTl_, g_wqkvTl);
    cudaGetSymbolAddress((void**)&woTh_,   g_woTh);
    cudaGetSymbolAddress((void**)&woTl_,   g_woTl);
    cudaGetSymbolAddress((void**)&wfcTh_,  g_wfcTh);
    cudaGetSymbolAddress((void**)&wfcTl_,  g_wfcTl);
    cudaGetSymbolAddress((void**)&wpwTh_,  g_wpwTh);
    cudaGetSymbolAddress((void**)&wpwTl_,  g_wpwTl);
    cudaGetSymbolAddress((void**)&wprojTh_,g_wprojTh);
    cudaGetSymbolAddress((void**)&wprojTl_,g_wprojTl);

    // ---- weight transposes + bf16 hi/lo conversion ----
    dim3 tb(32,8);
    transpose_bf<<<dim3(24,24,NLAYER),tb>>>(qw, (size_t)DD*DD, wqkvTh_ + 0*(size_t)DD*DD, wqkvTl_ + 0*(size_t)DD*DD, (size_t)3*DD*DD, DD, DD);
    transpose_bf<<<dim3(24,24,NLAYER),tb>>>(kw, (size_t)DD*DD, wqkvTh_ + 1*(size_t)DD*DD, wqkvTl_ + 1*(size_t)DD*DD, (size_t)3*DD*DD, DD, DD);
    transpose_bf<<<dim3(24,24,NLAYER),tb>>>(vw, (size_t)DD*DD, wqkvTh_ + 2*(size_t)DD*DD, wqkvTl_ + 2*(size_t)DD*DD, (size_t)3*DD*DD, DD, DD);
    transpose_bf<<<dim3(24,24,NLAYER),tb>>>(ow, (size_t)DD*DD, woTh_, woTl_, (size_t)DD*DD, DD, DD);
    transpose_bf<<<dim3(96,24,NLAYER),tb>>>(fcw,(size_t)DD*MLPD, wfcTh_, wfcTl_, (size_t)MLPD*DD, DD, MLPD);
    transpose_bf<<<dim3(24,96,NLAYER),tb>>>(pw, (size_t)MLPD*DD, wpwTh_, wpwTl_, (size_t)DD*MLPD, MLPD, DD);
    transpose_bf<<<dim3(24,24,1),tb>>>(proj_w, 0, wprojTh_, wprojTl_, 0, DD, DD);

    // ---- patch embed ----
    patch_gather<<<2048, 256>>>(x, th_, tl_);
    gemm_tc<0><<<dim3(6,36,1),256>>>(th_, tl_, wprojTh_, wprojTl_,
                                     proj_b,proj_b,proj_b, nullptr,
                                     emb_,emb_,emb_, nullptr,nullptr, PROWS, DD, DD);
    assemble<<<2048, 256>>>(emb_, cls, pos, h_);

    dim3 gD(6,37,1), gQKV(6,37,3), gFC(24,37,1);
    dim3 gSc((NTOK+63)/64, (NTOK+63)/64, BSZ*NHD);
    dim3 gAv((NTOK+63)/64, BSZ*NHD);

    for (int l=0; l<NLAYER; l++){
        layernorm_bf<<<ROWS,256>>>(h_, ln1_g+l*DD, ln1_b+l*DD, yh_, yl_, ROWS);
        gemm_tc<0><<<gQKV,256>>>(yh_, yl_,
                                 wqkvTh_ + (size_t)l*3*DD*DD, wqkvTl_ + (size_t)l*3*DD*DD,
                                 qb+l*DD, kb+l*DD, vb+l*DD, nullptr,
                                 q_, k_, v_, nullptr,nullptr, ROWS, DD, DD);
        attn_scores<<<gSc,256>>>(q_, k_, S_);
        softmax_k<<<BSZ*NHD*NTOK,256>>>(S_);
        attn_av<<<gAv,256>>>(S_, v_, aoh_, aol_);
        gemm_tc<1><<<gD,256>>>(aoh_, aol_,
                               woTh_ + (size_t)l*DD*DD, woTl_ + (size_t)l*DD*DD,
                               ob+l*DD, ob+l*DD, ob+l*DD, h_,
                               h_, h_, h_, nullptr,nullptr, ROWS, DD, DD);
        layernorm_bf<<<ROWS,256>>>(h_, ln2_g+l*DD, ln2_b+l*DD, yh_, yl_, ROWS);
        gemm_tc<2><<<gFC,256>>>(yh_, yl_,
                                wfcTh_ + (size_t)l*MLPD*DD, wfcTl_ + (size_t)l*MLPD*DD,
                                fcb+l*MLPD, fcb+l*MLPD, fcb+l*MLPD, nullptr,
                                nullptr,nullptr,nullptr, mh_, ml_, ROWS, MLPD, DD);
        gemm_tc<1><<<gD,256>>>(mh_, ml_,
                               wpwTh_ + (size_t)l*DD*MLPD, wpwTl_ + (size_t)l*DD*MLPD,
                               pb+l*DD, pb+l*DD, pb+l*DD, h_,
                               h_, h_, h_, nullptr,nullptr, ROWS, DD, MLPD);
    }

    layernorm_f<<<BSZ,256>>>(h_, (size_t)NTOK*DD, lnf_g, lnf_b, cls_, BSZ);
    gemm128<<<dim3((NCLS+127)/128,1),256>>>(cls_, head_w, head_b, out, BSZ, NCLS, DD);
}

// round 11
// speedup vs baseline: 2.1644x; 1.2110x over previous
#include <cuda_runtime.h>
#include <cuda_bf16.h>
#include <math.h>
#include <stdint.h>

// ---------------- problem constants ----------------
#define BSZ    8
#define CCH    3
#define IMH    384
#define IMW    384
#define PATCH  16
#define DD     768
#define NHD    12
#define HDD    64
#define MLPD   3072
#define NLAYER 12
#define NCLS   1000
#define GHH    24
#define GWW    24
#define NPATCH 576
#define NTOK   577
#define NTP    640              // padded token dim (10*64)
#define ROWS   (BSZ*NTOK)       // 4616
#define PROWS  (BSZ*NPATCH)     // 4608
#define EPSL   1e-5f
#define ATT_SCALE 0.125f

typedef __nv_bfloat16 bf16;
typedef __nv_bfloat162 bf162;

// ---------------- device scratch (no allocation allowed) ----------------
__device__ __align__(16) float g_emb[(size_t)PROWS*DD];
__device__ __align__(16) float g_h  [(size_t)ROWS*DD];
__device__ __align__(16) float g_S  [(size_t)BSZ*NHD*NTP*NTP];   // 157 MB
__device__ __align__(16) float g_cls[BSZ*DD];
// bf16 hi/lo activation buffers
__device__ __align__(16) bf16 g_th [(size_t)PROWS*DD];
__device__ __align__(16) bf16 g_tl [(size_t)PROWS*DD];
__device__ __align__(16) bf16 g_yh [(size_t)ROWS*DD];
__device__ __align__(16) bf16 g_yl [(size_t)ROWS*DD];
__device__ __align__(16) bf16 g_qh [(size_t)ROWS*DD];
__device__ __align__(16) bf16 g_ql [(size_t)ROWS*DD];
__device__ __align__(16) bf16 g_kh [(size_t)ROWS*DD];
__device__ __align__(16) bf16 g_kl [(size_t)ROWS*DD];
__device__ __align__(16) bf16 g_vth[(size_t)BSZ*DD*NTP];
__device__ __align__(16) bf16 g_vtl[(size_t)BSZ*DD*NTP];
__device__ __align__(16) bf16 g_ph [(size_t)BSZ*NHD*NTP*NTP];    // 78.6 MB
__device__ __align__(16) bf16 g_pl [(size_t)BSZ*NHD*NTP*NTP];
__device__ __align__(16) bf16 g_aoh[(size_t)ROWS*DD];
__device__ __align__(16) bf16 g_aol[(size_t)ROWS*DD];
__device__ __align__(16) bf16 g_mh [(size_t)ROWS*MLPD];
__device__ __align__(16) bf16 g_ml [(size_t)ROWS*MLPD];
// transposed weights [N][K] row-major, bf16 hi/lo
__device__ __align__(16) bf16 g_wqkvTh[(size_t)NLAYER*3*DD*DD];
__device__ __align__(16) bf16 g_wqkvTl[(size_t)NLAYER*3*DD*DD];
__device__ __align__(16) bf16 g_woTh  [(size_t)NLAYER*DD*DD];
__device__ __align__(16) bf16 g_woTl  [(size_t)NLAYER*DD*DD];
__device__ __align__(16) bf16 g_wfcTh [(size_t)NLAYER*MLPD*DD];
__device__ __align__(16) bf16 g_wfcTl [(size_t)NLAYER*MLPD*DD];
__device__ __align__(16) bf16 g_wpwTh [(size_t)NLAYER*DD*MLPD];
__device__ __align__(16) bf16 g_wpwTl [(size_t)NLAYER*DD*MLPD];
__device__ __align__(16) bf16 g_wprojTh[(size_t)DD*DD];
__device__ __align__(16) bf16 g_wprojTl[(size_t)DD*DD];

// ---------------- helpers ----------------
__device__ __forceinline__ void f2pair(float x, bf16& h, bf16& l){
    h = __float2bfloat16_rn(x);
    l = __float2bfloat16_rn(x - __bfloat162float(h));
}
__device__ __forceinline__ uint32_t smem_u32(const void* p){
    uint32_t a;
    asm("{ .reg .u64 t; cvta.to.shared.u64 t, %1; cvt.u32.u64 %0, t; }" : "=r"(a) : "l"(p));
    return a;
}
__device__ __forceinline__ void ldsm4(uint32_t& r0, uint32_t& r1, uint32_t& r2, uint32_t& r3,
                                      uint32_t addr){
    asm volatile("ldmatrix.sync.aligned.m8n8.x4.shared.b16 {%0,%1,%2,%3}, [%4];"
        : "=r"(r0), "=r"(r1), "=r"(r2), "=r"(r3) : "r"(addr));
}
__device__ __forceinline__ void mma16816(float& d0, float& d1, float& d2, float& d3,
                                         uint32_t a0, uint32_t a1, uint32_t a2, uint32_t a3,
                                         uint32_t b0, uint32_t b1){
    asm volatile("mma.sync.aligned.m16n8k16.row.col.f32.bf16.bf16.f32 "
        "{%0,%1,%2,%3}, {%4,%5,%6,%7}, {%8,%9}, {%0,%1,%2,%3};"
        : "+f"(d0), "+f"(d1), "+f"(d2), "+f"(d3)
        : "r"(a0), "r"(a1), "r"(a2), "r"(a3), "r"(b0), "r"(b1));
}

// ---------------- small reductions ----------------
__device__ __forceinline__ float warp_sum(float v){
    #pragma unroll
    for (int o=16;o;o>>=1) v += __shfl_xor_sync(0xffffffffu, v, o);
    return v;
}
__device__ __forceinline__ float warp_max(float v){
    #pragma unroll
    for (int o=16;o;o>>=1) v = fmaxf(v, __shfl_xor_sync(0xffffffffu, v, o));
    return v;
}

// ---------------- patch gather -> bf16 hi/lo ----------------
__global__ void patch_gather(const float* __restrict__ x, bf16* __restrict__ th,
                             bf16* __restrict__ tl){
    const int MP = BSZ*CCH*GHH*GWW*PATCH;
    const int total = (int)((size_t)PROWS*DD);
    for (int idx = blockIdx.x*blockDim.x + threadIdx.x; idx < total;
         idx += gridDim.x*blockDim.x){
        int p1  = idx / MP;
        int rem = idx - p1*MP;
        int m   = rem >> 4;
        int p2  = rem & 15;
        int gw  = m % GWW;   int m2 = m / GWW;
        int gh  = m2 % GHH;  int m3 = m2 / GHH;
        int c   = m3 % CCH;  int b  = m3 / CCH;
        float v = x[(((size_t)b*CCH + c)*IMH + gh*PATCH + p1)*IMW + gw*PATCH + p2];
        bf16 h, l; f2pair(v, h, l);
        th[idx] = h; tl[idx] = l;
    }
}

// ---------------- assemble h = concat(cls, emb) + pos ----------------
__global__ void assemble(const float* __restrict__ emb, const float* __restrict__ cls,
                         const float* __restrict__ pos, float* __restrict__ h){
    const int total = (int)((size_t)ROWS*DD);
    for (int idx = blockIdx.x*blockDim.x + threadIdx.x; idx < total;
         idx += gridDim.x*blockDim.x){
        int d = idx % DD;
        int r = (idx / DD) % NTOK;
        int b = idx / (NTOK*DD);
        float v = (r==0) ? cls[d] : emb[((size_t)b*NPATCH + (r-1))*DD + d];
        h[idx] = v + pos[(size_t)r*DD + d];
    }
}

// ---------------- zero vT padding columns (cols NTOK..NTP-1) ----------------
__global__ void zero_vt_pad(bf16* __restrict__ vth, bf16* __restrict__ vtl){
    const int PADW = NTP - NTOK;              // 63
    const int total = BSZ*DD*PADW;
    for (int idx = blockIdx.x*blockDim.x + threadIdx.x; idx < total;
         idx += gridDim.x*blockDim.x){
        int row = idx / PADW, c = NTOK + idx % PADW;
        vth[(size_t)row*NTP + c] = __float2bfloat16_rn(0.f);
        vtl[(size_t)row*NTP + c] = __float2bfloat16_rn(0.f);
    }
}

// ---------------- transpose fp32 [z][R][C] -> bf16 hi/lo [z][C][R] ----------------
__global__ void transpose_bf(const float* __restrict__ src, size_t sz,
                             bf16* __restrict__ dh, bf16* __restrict__ dl,
                             size_t dz, int R, int C){
    __shared__ float t[32][33];
    src += (size_t)blockIdx.z * sz;
    dh  += (size_t)blockIdx.z * dz;
    dl  += (size_t)blockIdx.z * dz;
    int c0 = blockIdx.x*32, r0 = blockIdx.y*32;
    for (int j=threadIdx.y; j<32; j+=8){
        int r=r0+j, c=c0+threadIdx.x;
        if (r<R && c<C) t[j][threadIdx.x] = src[(size_t)r*C+c];
    }
    __syncthreads();
    for (int j=threadIdx.y; j<32; j+=8){
        int c=c0+j, r=r0+threadIdx.x;
        if (r<R && c<C){
            bf16 h, l; f2pair(t[threadIdx.x][j], h, l);
            dh[(size_t)c*R+r] = h; dl[(size_t)c*R+r] = l;
        }
    }
}

// ---------------- layernorm -> bf16 hi/lo pair ----------------
__global__ void layernorm_bf(const float* __restrict__ in,
                             const float* __restrict__ g, const float* __restrict__ bb,
                             bf16* __restrict__ oh, bf16* __restrict__ ol, int M){
    int row = blockIdx.x; if (row>=M) return;
    const float4* xr = (const float4*)(in + (size_t)row*DD);
    float s=0.f, ss=0.f;
    for (int i=threadIdx.x;i<DD/4;i+=256){
        float4 v=xr[i];
        s += v.x+v.y+v.z+v.w;
        ss = fmaf(v.x,v.x,fmaf(v.y,v.y,fmaf(v.z,v.z,fmaf(v.w,v.w,ss))));
    }
    __shared__ float rs[8], rss[8];
    int lane = threadIdx.x&31, wid = threadIdx.x>>5;
    s = warp_sum(s); ss = warp_sum(ss);
    if (lane==0){ rs[wid]=s; rss[wid]=ss; }
    __syncthreads();
    if (wid==0){
        float a  = (lane<8)? rs[lane]:0.f;
        float a2 = (lane<8)? rss[lane]:0.f;
        a = warp_sum(a); a2 = warp_sum(a2);
        if (lane==0){ rs[0]=a; rss[0]=a2; }
    }
    __syncthreads();
    float mean = rs[0] * (1.f/DD);
    float var  = rss[0]*(1.f/DD) - mean*mean;
    float inv  = rsqrtf(var + EPSL);
    const float2* x2 = (const float2*)(in + (size_t)row*DD);
    const float2* g2 = (const float2*)g;
    const float2* b2 = (const float2*)bb;
    bf162* oh2 = (bf162*)(oh + (size_t)row*DD);
    bf162* ol2 = (bf162*)(ol + (size_t)row*DD);
    for (int i=threadIdx.x;i<DD/2;i+=256){
        float2 v=x2[i], gg=g2[i], bv=b2[i];
        float r0=(v.x-mean)*inv*gg.x+bv.x, r1=(v.y-mean)*inv*gg.y+bv.y;
        bf162 hv, lv;
        f2pair(r0, hv.x, lv.x); f2pair(r1, hv.y, lv.y);
        oh2[i]=hv; ol2[i]=lv;
    }
}

// ---------------- layernorm fp32 out (final LN on CLS rows) ----------------
__global__ void layernorm_f(const float* __restrict__ in, size_t ld,
                            const float* __restrict__ g, const float* __restrict__ bb,
                            float* __restrict__ out, int M){
    int row = blockIdx.x; if (row>=M) return;
    const float* xr = in + (size_t)row*ld;
    float s=0.f, ss=0.f;
    for (int i=threadIdx.x;i<DD;i+=256){ float v=xr[i]; s+=v; ss=fmaf(v,v,ss); }
    __shared__ float rs[8], rss[8];
    int lane = threadIdx.x&31, wid = threadIdx.x>>5;
    s = warp_sum(s); ss = warp_sum(ss);
    if (lane==0){ rs[wid]=s; rss[wid]=ss; }
    __syncthreads();
    if (wid==0){
        float a  = (lane<8)? rs[lane]:0.f;
        float a2 = (lane<8)? rss[lane]:0.f;
        a = warp_sum(a); a2 = warp_sum(a2);
        if (lane==0){ rs[0]=a; rss[0]=a2; }
    }
    __syncthreads();
    float mean = rs[0] * (1.f/DD);
    float var  = rss[0]*(1.f/DD) - mean*mean;
    float inv  = rsqrtf(var + EPSL);
    for (int i=threadIdx.x;i<DD;i+=256)
        out[(size_t)row*DD+i] = (xr[i]-mean)*inv*g[i] + bb[i];
}

// ======================================================================
// mma.sync split-bf16 GEMM (validated round-9). MODE:
//  0 = bias -> fp32 C ; 1 = bias+resid -> fp32 C ; 2 = bias+GELU -> bf16 pair
//  3 = QKV: z=0 -> (bias)*ATT_SCALE -> Q pair (Ch/Cl); z=1 -> K pair (Kh2/Kl2);
//           z=2 -> V transposed into VTh/VTl [b*DD+n][NTP]
// ======================================================================
#define SKP 40
template<int MODE>
__global__ void __launch_bounds__(256)
gemm_tc(const bf16* __restrict__ Ah, const bf16* __restrict__ Al,
        const bf16* __restrict__ Bh0, const bf16* __restrict__ Bl0,
        const float* __restrict__ b0, const float* __restrict__ b1, const float* __restrict__ b2,
        const float* __restrict__ resid,
        float* C0, float* C1, float* C2,
        bf16* Ch, bf16* Cl,
        bf16* Kh2, bf16* Kl2, bf16* VTh, bf16* VTl,
        int M, int Nc, int K)
{
    __shared__ __align__(16) bf16 sAh[128*SKP];
    __shared__ __align__(16) bf16 sAl[128*SKP];
    __shared__ __align__(16) bf16 sBh[128*SKP];
    __shared__ __align__(16) bf16 sBl[128*SKP];

    const int z = blockIdx.z;
    const bf16* Bh = Bh0 + (size_t)z * Nc * K;
    const bf16* Bl = Bl0 + (size_t)z * Nc * K;
    const float* bias = (z==0)?b0:((z==1)?b1:b2);
    float* C = (z==0)?C0:((z==1)?C1:C2);

    const int tid = threadIdx.x, wid = tid>>5, lane = tid&31;
    const int warp_m = wid>>2, warp_n = wid&3;
    const int row0 = blockIdx.y*128, col0 = blockIdx.x*128;

    const int lrow = tid>>1, lk = (tid&1)*16;
    const bool aval = (row0+lrow) < M;
    const bf16* pAh = Ah + (size_t)(row0+lrow)*K + lk;
    const bf16* pAl = Al + (size_t)(row0+lrow)*K + lk;
    const bf16* pBh = Bh + (size_t)(col0+lrow)*K + lk;
    const bf16* pBl = Bl + (size_t)(col0+lrow)*K + lk;
    const int soff = lrow*SKP + lk;
    const uint4 zz = make_uint4(0,0,0,0);

    const int a_m = warp_m*64 + (lane&7) + ((lane>>3)&1)*8;
    const int a_k = (lane>>4)*8;
    const uint32_t aAh = smem_u32(sAh) + (uint32_t)(a_m*SKP + a_k)*2;
    const uint32_t aAl = smem_u32(sAl) + (uint32_t)(a_m*SKP + a_k)*2;
    const int b_n = warp_n*32 + (lane&7) + (lane>>4)*8;
    const int b_k = ((lane>>3)&1)*8;
    const uint32_t aBh = smem_u32(sBh) + (uint32_t)(b_n*SKP + b_k)*2;
    const uint32_t aBl = smem_u32(sBl) + (uint32_t)(b_n*SKP + b_k)*2;

    float acc[4][4][4];
    #pragma unroll
    for (int i=0;i<4;i++)
        #pragma unroll
        for (int j=0;j<4;j++)
            #pragma unroll
            for (int r=0;r<4;r++) acc[i][j][r]=0.f;

    const int NCH = K>>5;
    uint4 ra0, ra1, rb0, rb1, rc0, rc1, rd0, rd1;

    ra0 = aval ? *(const uint4*)(pAh)     : zz;
    ra1 = aval ? *(const uint4*)(pAh + 8) : zz;
    rb0 = aval ? *(const uint4*)(pAl)     : zz;
    rb1 = aval ? *(const uint4*)(pAl + 8) : zz;
    rc0 = *(const uint4*)(pBh);      rc1 = *(const uint4*)(pBh + 8);
    rd0 = *(const uint4*)(pBl);      rd1 = *(const uint4*)(pBl + 8);
    *(uint4*)(&sAh[soff]) = ra0; *(uint4*)(&sAh[soff+8]) = ra1;
    *(uint4*)(&sAl[soff]) = rb0; *(uint4*)(&sAl[soff+8]) = rb1;
    *(uint4*)(&sBh[soff]) = rc0; *(uint4*)(&sBh[soff+8]) = rc1;
    *(uint4*)(&sBl[soff]) = rd0; *(uint4*)(&sBl[soff+8]) = rd1;
    __syncthreads();

    for (int ch=0; ch<NCH; ch++){
        if (ch+1 < NCH){
            int o = (ch+1)*32;
            ra0 = aval ? *(const uint4*)(pAh + o)     : zz;
            ra1 = aval ? *(const uint4*)(pAh + o + 8) : zz;
            rb0 = aval ? *(const uint4*)(pAl + o)     : zz;
            rb1 = aval ? *(const uint4*)(pAl + o + 8) : zz;
            rc0 = *(const uint4*)(pBh + o);  rc1 = *(const uint4*)(pBh + o + 8);
            rd0 = *(const uint4*)(pBl + o);  rd1 = *(const uint4*)(pBl + o + 8);
        }
        #pragma unroll
        for (int k16=0;k16<2;k16++){
            const uint32_t ko = (uint32_t)k16*32;
            uint32_t af[4][4], bh[2][4], bl[2][4];
            #pragma unroll
            for (int i=0;i<4;i++)
                ldsm4(af[i][0],af[i][1],af[i][2],af[i][3], aAh + i*16*SKP*2 + ko);
            #pragma unroll
            for (int p=0;p<2;p++)
                ldsm4(bh[p][0],bh[p][1],bh[p][2],bh[p][3], aBh + p*16*SKP*2 + ko);
            #pragma unroll
            for (int p=0;p<2;p++)
                ldsm4(bl[p][0],bl[p][1],bl[p][2],bl[p][3], aBl + p*16*SKP*2 + ko);
            #pragma unroll
            for (int i=0;i<4;i++)
                #pragma unroll
                for (int j=0;j<4;j++)
                    mma16816(acc[i][j][0],acc[i][j][1],acc[i][j][2],acc[i][j][3],
                             af[i][0],af[i][1],af[i][2],af[i][3],
                             bh[j>>1][(j&1)*2], bh[j>>1][(j&1)*2+1]);
            #pragma unroll
            for (int i=0;i<4;i++)
                #pragma unroll
                for (int j=0;j<4;j++)
                    mma16816(acc[i][j][0],acc[i][j][1],acc[i][j][2],acc[i][j][3],
                             af[i][0],af[i][1],af[i][2],af[i][3],
                             bl[j>>1][(j&1)*2], bl[j>>1][(j&1)*2+1]);
            #pragma unroll
            for (int i=0;i<4;i++)
                ldsm4(af[i][0],af[i][1],af[i][2],af[i][3], aAl + i*16*SKP*2 + ko);
            #pragma unroll
            for (int i=0;i<4;i++)
                #pragma unroll
                for (int j=0;j<4;j++)
                    mma16816(acc[i][j][0],acc[i][j][1],acc[i][j][2],acc[i][j][3],
                             af[i][0],af[i][1],af[i][2],af[i][3],
                             bh[j>>1][(j&1)*2], bh[j>>1][(j&1)*2+1]);
        }
        __syncthreads();
        if (ch+1 < NCH){
            *(uint4*)(&sAh[soff]) = ra0; *(uint4*)(&sAh[soff+8]) = ra1;
            *(uint4*)(&sAl[soff]) = rb0; *(uint4*)(&sAl[soff+8]) = rb1;
            *(uint4*)(&sBh[soff]) = rc0; *(uint4*)(&sBh[soff+8]) = rc1;
            *(uint4*)(&sBl[soff]) = rd0; *(uint4*)(&sBl[soff+8]) = rd1;
            __syncthreads();
        }
    }

    #pragma unroll
    for (int i=0;i<4;i++){
        #pragma unroll
        for (int j=0;j<4;j++){
            int m0 = row0 + warp_m*64 + i*16 + (lane>>2);
            int n0 = col0 + warp_n*32 + j*8 + (lane&3)*2;
            float bs0 = bias[n0], bs1 = bias[n0+1];
            #pragma unroll
            for (int half=0; half<2; half++){
                int m = m0 + half*8;
                if (m >= M) continue;
                float v0 = acc[i][j][half*2]   + bs0;
                float v1 = acc[i][j][half*2+1] + bs1;
                if (MODE == 1){
                    const float2 rv = *(const float2*)(resid + (size_t)m*Nc + n0);
                    v0 += rv.x; v1 += rv.y;
                }
                if (MODE == 2){
                    v0 = 0.5f*v0*(1.f + erff(v0*0.70710678118654752f));
                    v1 = 0.5f*v1*(1.f + erff(v1*0.70710678118654752f));
                    bf162 hv, lv;
                    f2pair(v0, hv.x, lv.x); f2pair(v1, hv.y, lv.y);
                    *(bf162*)(Ch + (size_t)m*Nc + n0) = hv;
                    *(bf162*)(Cl + (size_t)m*Nc + n0) = lv;
                } else if (MODE == 3){
                    if (z < 2){
                        if (z == 0){ v0 *= ATT_SCALE; v1 *= ATT_SCALE; }
                        bf16* Oh = (z==0)? Ch : Kh2;
                        bf16* Ol = (z==0)? Cl : Kl2;
                        bf162 hv, lv;
                        f2pair(v0, hv.x, lv.x); f2pair(v1, hv.y, lv.y);
                        *(bf162*)(Oh + (size_t)m*Nc + n0) = hv;
                        *(bf162*)(Ol + (size_t)m*Nc + n0) = lv;
                    } else {
                        int bq = m / NTOK, t = m - bq*NTOK;
                        size_t r0 = ((size_t)bq*DD + n0)*NTP + t;
                        bf16 h0,l0,h1,l1;
                        f2pair(v0,h0,l0); f2pair(v1,h1,l1);
                        VTh[r0] = h0;      VTl[r0] = l0;
                        VTh[r0+NTP] = h1;  VTl[r0+NTP] = l1;
                    }
                } else {
                    float2 ov; ov.x=v0; ov.y=v1;
                    *(float2*)(C + (size_t)m*Nc + n0) = ov;
                }
            }
        }
    }
}

// ======================================================================
// attention scores: S = (Q*scale) @ K^T  via split-bf16 mma.sync
// grid (jt, it, bh); 128 threads; 64x64 tile; k=HDD=64
// ======================================================================
#define SK2 72
__global__ void __launch_bounds__(128)
attn_scores_tc(const bf16* __restrict__ Qh, const bf16* __restrict__ Ql,
               const bf16* __restrict__ Kh, const bf16* __restrict__ Kl,
               float* __restrict__ S){
    __shared__ __align__(16) bf16 sQh[64*SK2], sQl[64*SK2], sKh[64*SK2], sKl[64*SK2];
    int bh = blockIdx.z, b = bh/NHD, h = bh%NHD;
    int i0 = blockIdx.y*64, j0 = blockIdx.x*64;
    int tid = threadIdx.x, wid = tid>>5, lane = tid&31;
    const uint4 zz = make_uint4(0,0,0,0);
    for (int l = tid; l < 512; l += 128){
        int r = l>>3, sg = (l&7)*8;
        int qi = i0 + r, kj = j0 + r;
        size_t qoff = ((size_t)(b*NTOK + qi))*DD + h*HDD + sg;
        size_t koff = ((size_t)(b*NTOK + kj))*DD + h*HDD + sg;
        uint4 vqh = (qi<NTOK)? *(const uint4*)(Qh+qoff) : zz;
        uint4 vql = (qi<NTOK)? *(const uint4*)(Ql+qoff) : zz;
        uint4 vkh = (kj<NTOK)? *(const uint4*)(Kh+koff) : zz;
        uint4 vkl = (kj<NTOK)? *(const uint4*)(Kl+koff) : zz;
        *(uint4*)(&sQh[r*SK2+sg]) = vqh;
        *(uint4*)(&sQl[r*SK2+sg]) = vql;
        *(uint4*)(&sKh[r*SK2+sg]) = vkh;
        *(uint4*)(&sKl[r*SK2+sg]) = vkl;
    }
    __syncthreads();
    int a_m = wid*16 + (lane&7) + ((lane>>3)&1)*8;
    int a_k = (lane>>4)*8;
    uint32_t aQh = smem_u32(sQh) + (uint32_t)(a_m*SK2 + a_k)*2;
    uint32_t aQl = smem_u32(sQl) + (uint32_t)(a_m*SK2 + a_k)*2;
    int b_n = (lane&7) + (lane>>4)*8;
    int b_k = ((lane>>3)&1)*8;
    uint32_t aKh = smem_u32(sKh) + (uint32_t)(b_n*SK2 + b_k)*2;
    uint32_t aKl = smem_u32(sKl) + (uint32_t)(b_n*SK2 + b_k)*2;

    float acc[8][4];
    #pragma unroll
    for (int j=0;j<8;j++)
        #pragma unroll
        for (int r=0;r<4;r++) acc[j][r]=0.f;

    #pragma unroll
    for (int k16=0;k16<4;k16++){
        uint32_t ko = (uint32_t)k16*32;
        uint32_t qh_[4], ql_[4], kh_[4][4], kl_[4][4];
        ldsm4(qh_[0],qh_[1],qh_[2],qh_[3], aQh + ko);
        ldsm4(ql_[0],ql_[1],ql_[2],ql_[3], aQl + ko);
        #pragma unroll
        for (int p=0;p<4;p++){
            ldsm4(kh_[p][0],kh_[p][1],kh_[p][2],kh_[p][3], aKh + (uint32_t)p*16*SK2*2 + ko);
            ldsm4(kl_[p][0],kl_[p][1],kl_[p][2],kl_[p][3], aKl + (uint32_t)p*16*SK2*2 + ko);
        }
        #pragma unroll
        for (int j=0;j<8;j++)
            mma16816(acc[j][0],acc[j][1],acc[j][2],acc[j][3],
                     qh_[0],qh_[1],qh_[2],qh_[3],
                     kh_[j>>1][(j&1)*2], kh_[j>>1][(j&1)*2+1]);
        #pragma unroll
        for (int j=0;j<8;j++)
            mma16816(acc[j][0],acc[j][1],acc[j][2],acc[j][3],
                     qh_[0],qh_[1],qh_[2],qh_[3],
                     kl_[j>>1][(j&1)*2], kl_[j>>1][(j&1)*2+1]);
        #pragma unroll
        for (int j=0;j<8;j++)
            mma16816(acc[j][0],acc[j][1],acc[j][2],acc[j][3],
                     ql_[0],ql_[1],ql_[2],ql_[3],
                     kh_[j>>1][(j&1)*2], kh_[j>>1][(j&1)*2+1]);
    }
    float* sp = S + (size_t)bh*NTP*NTP;
    #pragma unroll
    for (int j=0;j<8;j++){
        int n0 = j0 + j*8 + (lane&3)*2;
        #pragma unroll
        for (int half=0;half<2;half++){
            int m = i0 + wid*16 + (lane>>2) + half*8;
            if (m < NTOK){
                sp[(size_t)m*NTP + n0]   = acc[j][half*2];
                sp[(size_t)m*NTP + n0+1] = acc[j][half*2+1];
            }
        }
    }
}

// ---------------- softmax: S row -> P bf16 hi/lo (zero-padded to NTP) ----------------
__global__ void __launch_bounds__(256)
softmax_bf(const float* __restrict__ S, bf16* __restrict__ Ph, bf16* __restrict__ Pl){
    __shared__ float buf[NTP];
    __shared__ float sh[8];
    int bh = blockIdx.y, q = blockIdx.x;
    const float* r = S + ((size_t)bh*NTP + q)*NTP;
    int lane = threadIdx.x&31, wid = threadIdx.x>>5;
    float mx = -3.4e38f;
    for (int i=threadIdx.x;i<NTOK;i+=256){ float v=r[i]; buf[i]=v; mx=fmaxf(mx,v); }
    mx = warp_max(mx);
    if (lane==0) sh[wid]=mx;
    __syncthreads();
    if (wid==0){
        float a = (lane<8)? sh[lane] : -3.4e38f;
        a = warp_max(a);
        if (lane==0) sh[0]=a;
    }
    __syncthreads();
    float M = sh[0];
    __syncthreads();
    float s = 0.f;
    for (int i=threadIdx.x;i<NTOK;i+=256){ float e = expf(buf[i]-M); buf[i]=e; s+=e; }
    s = warp_sum(s);
    if (lane==0) sh[wid]=s;
    __syncthreads();
    if (wid==0){
        float a = (lane<8)? sh[lane] : 0.f;
        a = warp_sum(a);
        if (lane==0) sh[0]=a;
    }
    __syncthreads();
    float inv = 1.f/sh[0];
    bf162* ph2 = (bf162*)(Ph + ((size_t)bh*NTP + q)*NTP);
    bf162* pl2 = (bf162*)(Pl + ((size_t)bh*NTP + q)*NTP);
    for (int i=threadIdx.x;i<NTP/2;i+=256){
        int j0 = i*2;
        float v0 = (j0   < NTOK)? buf[j0]*inv   : 0.f;
        float v1 = (j0+1 < NTOK)? buf[j0+1]*inv : 0.f;
        bf162 hv, lv;
        f2pair(v0, hv.x, lv.x); f2pair(v1, hv.y, lv.y);
        ph2[i]=hv; pl2[i]=lv;
    }
}

// ======================================================================
// attention AV: O = P @ V  via split-bf16 mma.sync
// grid (it, bh); 128 threads; m=64 queries x n=64 hd; k over NTP tokens
// ======================================================================
__global__ void __launch_bounds__(128)
attn_av_tc(const bf16* __restrict__ Ph, const bf16* __restrict__ Pl,
           const bf16* __restrict__ VTh, const bf16* __restrict__ VTl,
           bf16* __restrict__ Oh, bf16* __restrict__ Ol){
    __shared__ __align__(16) bf16 sPh[64*SK2], sPl[64*SK2], sVh[64*SK2], sVl[64*SK2];
    int bh = blockIdx.y, b = bh/NHD, h = bh%NHD;
    int i0 = blockIdx.x*64;
    int tid = threadIdx.x, wid = tid>>5, lane = tid&31;

    int a_m = wid*16 + (lane&7) + ((lane>>3)&1)*8;
    int a_k = (lane>>4)*8;
    uint32_t aPh = smem_u32(sPh) + (uint32_t)(a_m*SK2 + a_k)*2;
    uint32_t aPl = smem_u32(sPl) + (uint32_t)(a_m*SK2 + a_k)*2;
    int b_n = (lane&7) + (lane>>4)*8;
    int b_k = ((lane>>3)&1)*8;
    uint32_t aVh = smem_u32(sVh) + (uint32_t)(b_n*SK2 + b_k)*2;
    uint32_t aVl = smem_u32(sVl) + (uint32_t)(b_n*SK2 + b_k)*2;

    float acc[8][4];
    #pragma unroll
    for (int j=0;j<8;j++)
        #pragma unroll
        for (int r=0;r<4;r++) acc[j][r]=0.f;

    for (int chk=0; chk<NTP/64; chk++){
        for (int l = tid; l < 512; l += 128){
            int r = l>>3, sg = (l&7)*8;
            size_t poff = ((size_t)bh*NTP + i0 + r)*NTP + chk*64 + sg;
            size_t voff = ((size_t)b*DD + h*HDD + r)*NTP + chk*64 + sg;
            *(uint4*)(&sPh[r*SK2+sg]) = *(const uint4*)(Ph+poff);
            *(uint4*)(&sPl[r*SK2+sg]) = *(const uint4*)(Pl+poff);
            *(uint4*)(&sVh[r*SK2+sg]) = *(const uint4*)(VTh+voff);
            *(uint4*)(&sVl[r*SK2+sg]) = *(const uint4*)(VTl+voff);
        }
        __syncthreads();
        #pragma unroll
        for (int k16=0;k16<4;k16++){
            uint32_t ko = (uint32_t)k16*32;
            uint32_t ph_[4], pl_[4], vh_[4][4], vl_[4][4];
            ldsm4(ph_[0],ph_[1],ph_[2],ph_[3], aPh + ko);
            ldsm4(pl_[0],pl_[1],pl_[2],pl_[3], aPl + ko);
            #pragma unroll
            for (int p=0;p<4;p++){
                ldsm4(vh_[p][0],vh_[p][1],vh_[p][2],vh_[p][3], aVh + (uint32_t)p*16*SK2*2 + ko);
                ldsm4(vl_[p][0],vl_[p][1],vl_[p][2],vl_[p][3], aVl + (uint32_t)p*16*SK2*2 + ko);
            }
            #pragma unroll
            for (int j=0;j<8;j++)
                mma16816(acc[j][0],acc[j][1],acc[j][2],acc[j][3],
                         ph_[0],ph_[1],ph_[2],ph_[3],
                         vh_[j>>1][(j&1)*2], vh_[j>>1][(j&1)*2+1]);
            #pragma unroll
            for (int j=0;j<8;j++)
                mma16816(acc[j][0],acc[j][1],acc[j][2],acc[j][3],
                         ph_[0],ph_[1],ph_[2],ph_[3],
                         vl_[j>>1][(j&1)*2], vl_[j>>1][(j&1)*2+1]);
            #pragma unroll
            for (int j=0;j<8;j++)
                mma16816(acc[j][0],acc[j][1],acc[j][2],acc[j][3],
                         pl_[0],pl_[1],pl_[2],pl_[3],
                         vh_[j>>1][(j&1)*2], vh_[j>>1][(j&1)*2+1]);
        }
        __syncthreads();
    }
    #pragma unroll
    for (int j=0;j<8;j++){
        int n0 = h*HDD + j*8 + (lane&3)*2;
        #pragma unroll
        for (int half=0;half<2;half++){
            int m = i0 + wid*16 + (lane>>2) + half*8;
            if (m < NTOK){
                bf162 hv, lv;
                f2pair(acc[j][half*2],   hv.x, lv.x);
                f2pair(acc[j][half*2+1], hv.y, lv.y);
                size_t o = ((size_t)(b*NTOK + m))*DD + n0;
                *(bf162*)(Oh + o) = hv;
                *(bf162*)(Ol + o) = lv;
            }
        }
    }
}

// ---------------- SIMT gemm for the tiny head GEMM ----------------
__global__ void __launch_bounds__(256)
gemm128(const float* __restrict__ A, const float* __restrict__ Wt,
        const float* __restrict__ bias, float* __restrict__ Cc,
        int M, int Nc, int K){
    __shared__ __align__(16) float As[8][132];
    __shared__ __align__(16) float Bs[8][128];
    int tid = threadIdx.x;
    int tx = tid & 15, ty = tid >> 4;
    int row0 = blockIdx.y * 128, col0 = blockIdx.x * 128;
    float acc[8][8];
    #pragma unroll
    for (int i=0;i<8;i++)
        #pragma unroll
        for (int j=0;j<8;j++) acc[i][j]=0.f;
    for (int k0=0;k0<K;k0+=8){
        #pragma unroll
        for (int t=0;t<4;t++){
            int lin = tid*4+t;
            int r = lin>>3, c = lin&7;
            int gr = row0+r;
            As[c][r] = (gr<M) ? A[(size_t)gr*K + k0 + c] : 0.f;
        }
        #pragma unroll
        for (int t=0;t<4;t++){
            int lin = tid*4+t;
            int r = lin>>7, c = lin&127;
            int gc = col0+c;
            Bs[r][c] = (gc<Nc) ? Wt[(size_t)(k0+r)*Nc + gc] : 0.f;
        }
        __syncthreads();
        #pragma unroll
        for (int k=0;k<8;k++){
            float av[8], bv[8];
            #pragma unroll
            for (int i=0;i<8;i++) av[i]=As[k][ty*8+i];
            #pragma unroll
            for (int j=0;j<8;j++) bv[j]=Bs[k][tx*8+j];
            #pragma unroll
            for (int i=0;i<8;i++)
                #pragma unroll
                for (int j=0;j<8;j++)
                    acc[i][j] = fmaf(av[i], bv[j], acc[i][j]);
        }
        __syncthreads();
    }
    #pragma unroll
    for (int i=0;i<8;i++){
        int gr = row0 + ty*8 + i;
        if (gr>=M) continue;
        #pragma unroll
        for (int j=0;j<8;j++){
            int gc = col0 + tx*8 + j;
            if (gc>=Nc) continue;
            Cc[(size_t)gr*Nc + gc] = acc[i][j] + bias[gc];
        }
    }
}

// ---------------- host driver ----------------
extern "C" void kernel_launch(void* const* d_in, const int* in_sizes, int n_in,
                              void* d_out, int out_size){
    const float* x      = (const float*)d_in[0];
    const float* proj_w = (const float*)d_in[1];
    const float* proj_b = (const float*)d_in[2];
    const float* cls    = (const float*)d_in[3];
    const float* pos    = (const float*)d_in[4];
    const float* ln1_g  = (const float*)d_in[5];
    const float* ln1_b  = (const float*)d_in[6];
    const float* qw = (const float*)d_in[7];  const float* qb = (const float*)d_in[8];
    const float* kw = (const float*)d_in[9];  const float* kb = (const float*)d_in[10];
    const float* vw = (const float*)d_in[11]; const float* vb = (const float*)d_in[12];
    const float* ow = (const float*)d_in[13]; const float* ob = (const float*)d_in[14];
    const float* ln2_g = (const float*)d_in[15]; const float* ln2_b = (const float*)d_in[16];
    const float* fcw = (const float*)d_in[17]; const float* fcb = (const float*)d_in[18];
    const float* pw  = (const float*)d_in[19]; const float* pb  = (const float*)d_in[20];
    const float* lnf_g = (const float*)d_in[21]; const float* lnf_b = (const float*)d_in[22];
    const float* head_w = (const float*)d_in[23]; const float* head_b = (const float*)d_in[24];
    float* out = (float*)d_out;

    float *emb_, *h_, *S_, *cls_;
    bf16 *th_, *tl_, *yh_, *yl_, *qh_, *ql_, *kh_, *kl_, *vth_, *vtl_;
    bf16 *ph_, *pl_, *aoh_, *aol_, *mh_, *ml_;
    bf16 *wqkvTh_, *wqkvTl_, *woTh_, *woTl_, *wfcTh_, *wfcTl_, *wpwTh_, *wpwTl_, *wprojTh_, *wprojTl_;
    cudaGetSymbolAddress((void**)&emb_,g_emb);
    cudaGetSymbolAddress((void**)&h_,  g_h);
    cudaGetSymbolAddress((void**)&S_,  g_S);
    cudaGetSymbolAddress((void**)&cls_,g_cls);
    cudaGetSymbolAddress((void**)&th_, g_th);
    cudaGetSymbolAddress((void**)&tl_, g_tl);
    cudaGetSymbolAddress((void**)&yh_, g_yh);
    cudaGetSymbolAddress((void**)&yl_, g_yl);
    cudaGetSymbolAddress((void**)&qh_, g_qh);
    cudaGetSymbolAddress((void**)&ql_, g_ql);
    cudaGetSymbolAddress((void**)&kh_, g_kh);
    cudaGetSymbolAddress((void**)&kl_, g_kl);
    cudaGetSymbolAddress((void**)&vth_,g_vth);
    cudaGetSymbolAddress((void**)&vtl_,g_vtl);
    cudaGetSymbolAddress((void**)&ph_, g_ph);
    cudaGetSymbolAddress((void**)&pl_, g_pl);
    cudaGetSymbolAddress((void**)&aoh_,g_aoh);
    cudaGetSymbolAddress((void**)&aol_,g_aol);
    cudaGetSymbolAddress((void**)&mh_, g_mh);
    cudaGetSymbolAddress((void**)&ml_, g_ml);
    cudaGetSymbolAddress((void**)&wqkvTh_, g_wqkvTh);
    cudaGetSymbolAddress((void**)&wqkvTl_, g_wqkvTl);
    cudaGetSymbolAddress((void**)&woTh_,   g_woTh);
    cudaGetSymbolAddress((void**)&woTl_,   g_woTl);
    cudaGetSymbolAddress((void**)&wfcTh_,  g_wfcTh);
    cudaGetSymbolAddress((void**)&wfcTl_,  g_wfcTl);
    cudaGetSymbolAddress((void**)&wpwTh_,  g_wpwTh);
    cudaGetSymbolAddress((void**)&wpwTl_,  g_wpwTl);
    cudaGetSymbolAddress((void**)&wprojTh_,g_wprojTh);
    cudaGetSymbolAddress((void**)&wprojTl_,g_wprojTl);

    // ---- weight transposes + bf16 hi/lo conversion ----
    dim3 tb(32,8);
    transpose_bf<<<dim3(24,24,NLAYER),tb>>>(qw, (size_t)DD*DD, wqkvTh_ + 0*(size_t)DD*DD, wqkvTl_ + 0*(size_t)DD*DD, (size_t)3*DD*DD, DD, DD);
    transpose_bf<<<dim3(24,24,NLAYER),tb>>>(kw, (size_t)DD*DD, wqkvTh_ + 1*(size_t)DD*DD, wqkvTl_ + 1*(size_t)DD*DD, (size_t)3*DD*DD, DD, DD);
    transpose_bf<<<dim3(24,24,NLAYER),tb>>>(vw, (size_t)DD*DD, wqkvTh_ + 2*(size_t)DD*DD, wqkvTl_ + 2*(size_t)DD*DD, (size_t)3*DD*DD, DD, DD);
    transpose_bf<<<dim3(24,24,NLAYER),tb>>>(ow, (size_t)DD*DD, woTh_, woTl_, (size_t)DD*DD, DD, DD);
    transpose_bf<<<dim3(96,24,NLAYER),tb>>>(fcw,(size_t)DD*MLPD, wfcTh_, wfcTl_, (size_t)MLPD*DD, DD, MLPD);
    transpose_bf<<<dim3(24,96,NLAYER),tb>>>(pw, (size_t)MLPD*DD, wpwTh_, wpwTl_, (size_t)DD*MLPD, MLPD, DD);
    transpose_bf<<<dim3(24,24,1),tb>>>(proj_w, 0, wprojTh_, wprojTl_, 0, DD, DD);
    zero_vt_pad<<<512,256>>>(vth_, vtl_);

    // ---- patch embed ----
    patch_gather<<<2048, 256>>>(x, th_, tl_);
    gemm_tc<0><<<dim3(6,36,1),256>>>(th_, tl_, wprojTh_, wprojTl_,
                                     proj_b,proj_b,proj_b, nullptr,
                                     emb_,emb_,emb_, nullptr,nullptr,
                                     nullptr,nullptr,nullptr,nullptr, PROWS, DD, DD);
    assemble<<<2048, 256>>>(emb_, cls, pos, h_);

    dim3 gD(6,37,1), gQKV(6,37,3), gFC(24,37,1);
    dim3 gSc(NTP/64, NTP/64, BSZ*NHD);
    dim3 gSm(NTOK, BSZ*NHD);
    dim3 gAv(NTP/64, BSZ*NHD);

    for (int l=0; l<NLAYER; l++){
        layernorm_bf<<<ROWS,256>>>(h_, ln1_g+l*DD, ln1_b+l*DD, yh_, yl_, ROWS);
        gemm_tc<3><<<gQKV,256>>>(yh_, yl_,
                                 wqkvTh_ + (size_t)l*3*DD*DD, wqkvTl_ + (size_t)l*3*DD*DD,
                                 qb+l*DD, kb+l*DD, vb+l*DD, nullptr,
                                 nullptr,nullptr,nullptr,
                                 qh_, ql_, kh_, kl_, vth_, vtl_, ROWS, DD, DD);
        attn_scores_tc<<<gSc,128>>>(qh_, ql_, kh_, kl_, S_);
        softmax_bf<<<gSm,256>>>(S_, ph_, pl_);
        attn_av_tc<<<gAv,128>>>(ph_, pl_, vth_, vtl_, aoh_, aol_);
        gemm_tc<1><<<gD,256>>>(aoh_, aol_,
                               woTh_ + (size_t)l*DD*DD, woTl_ + (size_t)l*DD*DD,
                               ob+l*DD, ob+l*DD, ob+l*DD, h_,
                               h_, h_, h_, nullptr,nullptr,
                               nullptr,nullptr,nullptr,nullptr, ROWS, DD, DD);
        layernorm_bf<<<ROWS,256>>>(h_, ln2_g+l*DD, ln2_b+l*DD, yh_, yl_, ROWS);
        gemm_tc<2><<<gFC,256>>>(yh_, yl_,
                                wfcTh_ + (size_t)l*MLPD*DD, wfcTl_ + (size_t)l*MLPD*DD,
                                fcb+l*MLPD, fcb+l*MLPD, fcb+l*MLPD, nullptr,
                                nullptr,nullptr,nullptr, mh_, ml_,
                                nullptr,nullptr,nullptr,nullptr, ROWS, MLPD, DD);
        gemm_tc<1><<<gD,256>>>(mh_, ml_,
                               wpwTh_ + (size_t)l*DD*MLPD, wpwTl_ + (size_t)l*DD*MLPD,
                               pb+l*DD, pb+l*DD, pb+l*DD, h_,
                               h_, h_, h_, nullptr,nullptr,
                               nullptr,nullptr,nullptr,nullptr, ROWS, DD, MLPD);
    }

    layernorm_f<<<BSZ,256>>>(h_, (size_t)NTOK*DD, lnf_g, lnf_b, cls_, BSZ);
    gemm128<<<dim3((NCLS+127)/128,1),256>>>(cls_, head_w, head_b, out, BSZ, NCLS, DD);
}

// round 12
// speedup vs baseline: 2.2881x; 1.0571x over previous
#include <cuda_runtime.h>
#include <cuda_bf16.h>
#include <math.h>
#include <stdint.h>

// ---------------- problem constants ----------------
#define BSZ    8
#define CCH    3
#define IMH    384
#define IMW    384
#define PATCH  16
#define DD     768
#define NHD    12
#define HDD    64
#define MLPD   3072
#define NLAYER 12
#define NCLS   1000
#define GHH    24
#define GWW    24
#define NPATCH 576
#define NTOK   577
#define NTP    640              // padded token dim (10*64)
#define ROWS   (BSZ*NTOK)       // 4616
#define PROWS  (BSZ*NPATCH)     // 4608
#define EPSL   1e-5f
#define ATT_SCALE 0.125f

typedef __nv_bfloat16 bf16;
typedef __nv_bfloat162 bf162;

// ---------------- device scratch (no allocation allowed) ----------------
__device__ __align__(16) float g_emb[(size_t)PROWS*DD];
__device__ __align__(16) float g_h  [(size_t)ROWS*DD];
__device__ __align__(16) float g_S  [(size_t)BSZ*NHD*NTP*NTP];   // 157 MB
__device__ __align__(16) float g_cls[BSZ*DD];
// bf16 hi/lo activation buffers
__device__ __align__(16) bf16 g_th [(size_t)PROWS*DD];
__device__ __align__(16) bf16 g_tl [(size_t)PROWS*DD];
__device__ __align__(16) bf16 g_yh [(size_t)ROWS*DD];
__device__ __align__(16) bf16 g_yl [(size_t)ROWS*DD];
__device__ __align__(16) bf16 g_qh [(size_t)ROWS*DD];
__device__ __align__(16) bf16 g_ql [(size_t)ROWS*DD];
__device__ __align__(16) bf16 g_kh [(size_t)ROWS*DD];
__device__ __align__(16) bf16 g_kl [(size_t)ROWS*DD];
__device__ __align__(16) bf16 g_vth[(size_t)BSZ*DD*NTP];
__device__ __align__(16) bf16 g_vtl[(size_t)BSZ*DD*NTP];
__device__ __align__(16) bf16 g_ph [(size_t)BSZ*NHD*NTP*NTP];    // 78.6 MB
__device__ __align__(16) bf16 g_pl [(size_t)BSZ*NHD*NTP*NTP];
__device__ __align__(16) bf16 g_aoh[(size_t)ROWS*DD];
__device__ __align__(16) bf16 g_aol[(size_t)ROWS*DD];
__device__ __align__(16) bf16 g_mh [(size_t)ROWS*MLPD];
__device__ __align__(16) bf16 g_ml [(size_t)ROWS*MLPD];
// transposed weights [N][K] row-major, bf16 hi/lo
__device__ __align__(16) bf16 g_wqkvTh[(size_t)NLAYER*3*DD*DD];
__device__ __align__(16) bf16 g_wqkvTl[(size_t)NLAYER*3*DD*DD];
__device__ __align__(16) bf16 g_woTh  [(size_t)NLAYER*DD*DD];
__device__ __align__(16) bf16 g_woTl  [(size_t)NLAYER*DD*DD];
__device__ __align__(16) bf16 g_wfcTh [(size_t)NLAYER*MLPD*DD];
__device__ __align__(16) bf16 g_wfcTl [(size_t)NLAYER*MLPD*DD];
__device__ __align__(16) bf16 g_wpwTh [(size_t)NLAYER*DD*MLPD];
__device__ __align__(16) bf16 g_wpwTl [(size_t)NLAYER*DD*MLPD];
__device__ __align__(16) bf16 g_wprojTh[(size_t)DD*DD];
__device__ __align__(16) bf16 g_wprojTl[(size_t)DD*DD];

// ---------------- helpers ----------------
__device__ __forceinline__ void f2pair(float x, bf16& h, bf16& l){
    h = __float2bfloat16_rn(x);
    l = __float2bfloat16_rn(x - __bfloat162float(h));
}
__device__ __forceinline__ uint32_t smem_u32(const void* p){
    uint32_t a;
    asm("{ .reg .u64 t; cvta.to.shared.u64 t, %1; cvt.u32.u64 %0, t; }" : "=r"(a) : "l"(p));
    return a;
}
__device__ __forceinline__ void ldsm4(uint32_t& r0, uint32_t& r1, uint32_t& r2, uint32_t& r3,
                                      uint32_t addr){
    asm volatile("ldmatrix.sync.aligned.m8n8.x4.shared.b16 {%0,%1,%2,%3}, [%4];"
        : "=r"(r0), "=r"(r1), "=r"(r2), "=r"(r3) : "r"(addr));
}
__device__ __forceinline__ void mma16816(float& d0, float& d1, float& d2, float& d3,
                                         uint32_t a0, uint32_t a1, uint32_t a2, uint32_t a3,
                                         uint32_t b0, uint32_t b1){
    asm volatile("mma.sync.aligned.m16n8k16.row.col.f32.bf16.bf16.f32 "
        "{%0,%1,%2,%3}, {%4,%5,%6,%7}, {%8,%9}, {%0,%1,%2,%3};"
        : "+f"(d0), "+f"(d1), "+f"(d2), "+f"(d3)
        : "r"(a0), "r"(a1), "r"(a2), "r"(a3), "r"(b0), "r"(b1));
}
// cp.async 16B with runtime src-size (0 => zero-fill)
__device__ __forceinline__ void cpa16(uint32_t daddr, const void* g, int sz){
    asm volatile("cp.async.cg.shared.global [%0], [%1], 16, %2;"
        :: "r"(daddr), "l"(g), "r"(sz));
}
#define CPA_COMMIT() asm volatile("cp.async.commit_group;" ::: "memory")
#define CPA_WAIT1()  asm volatile("cp.async.wait_group 1;" ::: "memory")
#define CPA_WAIT0()  asm volatile("cp.async.wait_group 0;" ::: "memory")

// ---------------- small reductions ----------------
__device__ __forceinline__ float warp_sum(float v){
    #pragma unroll
    for (int o=16;o;o>>=1) v += __shfl_xor_sync(0xffffffffu, v, o);
    return v;
}
__device__ __forceinline__ float warp_max(float v){
    #pragma unroll
    for (int o=16;o;o>>=1) v = fmaxf(v, __shfl_xor_sync(0xffffffffu, v, o));
    return v;
}

// ---------------- patch gather -> bf16 hi/lo ----------------
__global__ void patch_gather(const float* __restrict__ x, bf16* __restrict__ th,
                             bf16* __restrict__ tl){
    const int MP = BSZ*CCH*GHH*GWW*PATCH;
    const int total = (int)((size_t)PROWS*DD);
    for (int idx = blockIdx.x*blockDim.x + threadIdx.x; idx < total;
         idx += gridDim.x*blockDim.x){
        int p1  = idx / MP;
        int rem = idx - p1*MP;
        int m   = rem >> 4;
        int p2  = rem & 15;
        int gw  = m % GWW;   int m2 = m / GWW;
        int gh  = m2 % GHH;  int m3 = m2 / GHH;
        int c   = m3 % CCH;  int b  = m3 / CCH;
        float v = x[(((size_t)b*CCH + c)*IMH + gh*PATCH + p1)*IMW + gw*PATCH + p2];
        bf16 h, l; f2pair(v, h, l);
        th[idx] = h; tl[idx] = l;
    }
}

// ---------------- assemble h = concat(cls, emb) + pos ----------------
__global__ void assemble(const float* __restrict__ emb, const float* __restrict__ cls,
                         const float* __restrict__ pos, float* __restrict__ h){
    const int total = (int)((size_t)ROWS*DD);
    for (int idx = blockIdx.x*blockDim.x + threadIdx.x; idx < total;
         idx += gridDim.x*blockDim.x){
        int d = idx % DD;
        int r = (idx / DD) % NTOK;
        int b = idx / (NTOK*DD);
        float v = (r==0) ? cls[d] : emb[((size_t)b*NPATCH + (r-1))*DD + d];
        h[idx] = v + pos[(size_t)r*DD + d];
    }
}

// ---------------- zero vT padding columns (cols NTOK..NTP-1) ----------------
__global__ void zero_vt_pad(bf16* __restrict__ vth, bf16* __restrict__ vtl){
    const int PADW = NTP - NTOK;              // 63
    const int total = BSZ*DD*PADW;
    for (int idx = blockIdx.x*blockDim.x + threadIdx.x; idx < total;
         idx += gridDim.x*blockDim.x){
        int row = idx / PADW, c = NTOK + idx % PADW;
        vth[(size_t)row*NTP + c] = __float2bfloat16_rn(0.f);
        vtl[(size_t)row*NTP + c] = __float2bfloat16_rn(0.f);
    }
}

// ---------------- transpose fp32 [z][R][C] -> bf16 hi/lo [z][C][R] ----------------
__global__ void transpose_bf(const float* __restrict__ src, size_t sz,
                             bf16* __restrict__ dh, bf16* __restrict__ dl,
                             size_t dz, int R, int C){
    __shared__ float t[32][33];
    src += (size_t)blockIdx.z * sz;
    dh  += (size_t)blockIdx.z * dz;
    dl  += (size_t)blockIdx.z * dz;
    int c0 = blockIdx.x*32, r0 = blockIdx.y*32;
    for (int j=threadIdx.y; j<32; j+=8){
        int r=r0+j, c=c0+threadIdx.x;
        if (r<R && c<C) t[j][threadIdx.x] = src[(size_t)r*C+c];
    }
    __syncthreads();
    for (int j=threadIdx.y; j<32; j+=8){
        int c=c0+j, r=r0+threadIdx.x;
        if (r<R && c<C){
            bf16 h, l; f2pair(t[threadIdx.x][j], h, l);
            dh[(size_t)c*R+r] = h; dl[(size_t)c*R+r] = l;
        }
    }
}

// ---------------- layernorm -> bf16 hi/lo pair ----------------
__global__ void layernorm_bf(const float* __restrict__ in,
                             const float* __restrict__ g, const float* __restrict__ bb,
                             bf16* __restrict__ oh, bf16* __restrict__ ol, int M){
    int row = blockIdx.x; if (row>=M) return;
    const float4* xr = (const float4*)(in + (size_t)row*DD);
    float s=0.f, ss=0.f;
    for (int i=threadIdx.x;i<DD/4;i+=256){
        float4 v=xr[i];
        s += v.x+v.y+v.z+v.w;
        ss = fmaf(v.x,v.x,fmaf(v.y,v.y,fmaf(v.z,v.z,fmaf(v.w,v.w,ss))));
    }
    __shared__ float rs[8], rss[8];
    int lane = threadIdx.x&31, wid = threadIdx.x>>5;
    s = warp_sum(s); ss = warp_sum(ss);
    if (lane==0){ rs[wid]=s; rss[wid]=ss; }
    __syncthreads();
    if (wid==0){
        float a  = (lane<8)? rs[lane]:0.f;
        float a2 = (lane<8)? rss[lane]:0.f;
        a = warp_sum(a); a2 = warp_sum(a2);
        if (lane==0){ rs[0]=a; rss[0]=a2; }
    }
    __syncthreads();
    float mean = rs[0] * (1.f/DD);
    float var  = rss[0]*(1.f/DD) - mean*mean;
    float inv  = rsqrtf(var + EPSL);
    const float2* x2 = (const float2*)(in + (size_t)row*DD);
    const float2* g2 = (const float2*)g;
    const float2* b2 = (const float2*)bb;
    bf162* oh2 = (bf162*)(oh + (size_t)row*DD);
    bf162* ol2 = (bf162*)(ol + (size_t)row*DD);
    for (int i=threadIdx.x;i<DD/2;i+=256){
        float2 v=x2[i], gg=g2[i], bv=b2[i];
        float r0=(v.x-mean)*inv*gg.x+bv.x, r1=(v.y-mean)*inv*gg.y+bv.y;
        bf162 hv, lv;
        f2pair(r0, hv.x, lv.x); f2pair(r1, hv.y, lv.y);
        oh2[i]=hv; ol2[i]=lv;
    }
}

// ---------------- layernorm fp32 out (final LN on CLS rows) ----------------
__global__ void layernorm_f(const float* __restrict__ in, size_t ld,
                            const float* __restrict__ g, const float* __restrict__ bb,
                            float* __restrict__ out, int M){
    int row = blockIdx.x; if (row>=M) return;
    const float* xr = in + (size_t)row*ld;
    float s=0.f, ss=0.f;
    for (int i=threadIdx.x;i<DD;i+=256){ float v=xr[i]; s+=v; ss=fmaf(v,v,ss); }
    __shared__ float rs[8], rss[8];
    int lane = threadIdx.x&31, wid = threadIdx.x>>5;
    s = warp_sum(s); ss = warp_sum(ss);
    if (lane==0){ rs[wid]=s; rss[wid]=ss; }
    __syncthreads();
    if (wid==0){
        float a  = (lane<8)? rs[lane]:0.f;
        float a2 = (lane<8)? rss[lane]:0.f;
        a = warp_sum(a); a2 = warp_sum(a2);
        if (lane==0){ rs[0]=a; rss[0]=a2; }
    }
    __syncthreads();
    float mean = rs[0] * (1.f/DD);
    float var  = rss[0]*(1.f/DD) - mean*mean;
    float inv  = rsqrtf(var + EPSL);
    for (int i=threadIdx.x;i<DD;i+=256)
        out[(size_t)row*DD+i] = (xr[i]-mean)*inv*g[i] + bb[i];
}

// ======================================================================
// mma.sync split-bf16 GEMM — cp.async 2-stage double-buffered mainloop.
// MODE: 0 bias->fp32 ; 1 bias+resid->fp32 ; 2 bias+GELU->bf16 pair ;
//       3 QKV epilogue (Q pair scaled / K pair / V transposed)
// dyn smem: 2 stages x 4 arrays x 128 x SKP bf16 = 81920 B
// ======================================================================
#define SKP 40
#define ARRB (128*SKP*2)      // 10240 B per array
#define STGB2 (4*ARRB)        // 40960 B per stage
#define GT_DSMEM (2*STGB2)    // 81920 B
template<int MODE>
__global__ void __launch_bounds__(256, 2)
gemm_tc(const bf16* __restrict__ Ah, const bf16* __restrict__ Al,
        const bf16* __restrict__ Bh0, const bf16* __restrict__ Bl0,
        const float* __restrict__ b0, const float* __restrict__ b1, const float* __restrict__ b2,
        const float* __restrict__ resid,
        float* C0, float* C1, float* C2,
        bf16* Ch, bf16* Cl,
        bf16* Kh2, bf16* Kl2, bf16* VTh, bf16* VTl,
        int M, int Nc, int K)
{
    extern __shared__ __align__(16) bf16 smem[];
    const uint32_t sbase = smem_u32(smem);

    const int z = blockIdx.z;
    const bf16* Bh = Bh0 + (size_t)z * Nc * K;
    const bf16* Bl = Bl0 + (size_t)z * Nc * K;
    const float* bias = (z==0)?b0:((z==1)?b1:b2);
    float* C = (z==0)?C0:((z==1)?C1:C2);

    const int tid = threadIdx.x, wid = tid>>5, lane = tid&31;
    const int warp_m = wid>>2, warp_n = wid&3;
    const int row0 = blockIdx.y*128, col0 = blockIdx.x*128;

    // loader mapping: thread t -> row t>>1, k-halves (t&1)*16
    const int lrow = tid>>1, lk = (tid&1)*16;
    const bool aval = (row0+lrow) < M;
    const int asz = aval ? 16 : 0;
    const int arow = aval ? (row0+lrow) : 0;   // clamp (unused when asz=0)
    const bf16* pAh = Ah + (size_t)arow*K + lk;
    const bf16* pAl = Al + (size_t)arow*K + lk;
    const bf16* pBh = Bh + (size_t)(col0+lrow)*K + lk;
    const bf16* pBl = Bl + (size_t)(col0+lrow)*K + lk;
    const uint32_t dsto = (uint32_t)(lrow*SKP + lk)*2;   // bytes within array

    // ldmatrix lane addresses (within stage 0)
    const int a_m = warp_m*64 + (lane&7) + ((lane>>3)&1)*8;
    const int a_k = (lane>>4)*8;
    const uint32_t aAh = sbase + (uint32_t)(a_m*SKP + a_k)*2;
    const uint32_t aAl = aAh + ARRB;
    const int b_n = warp_n*32 + (lane&7) + (lane>>4)*8;
    const int b_k = ((lane>>3)&1)*8;
    const uint32_t aBh = sbase + 2*ARRB + (uint32_t)(b_n*SKP + b_k)*2;
    const uint32_t aBl = aBh + ARRB;

    float acc[4][4][4];
    #pragma unroll
    for (int i=0;i<4;i++)
        #pragma unroll
        for (int j=0;j<4;j++)
            #pragma unroll
            for (int r=0;r<4;r++) acc[i][j][r]=0.f;

    const int NCH = K>>5;

    // issue chunk ch into stage s
    auto issue = [&](int ch, int s){
        const int o = ch*32;
        const uint32_t d = sbase + (uint32_t)s*STGB2 + dsto;
        cpa16(d,              pAh + o,     asz);
        cpa16(d + 16,         pAh + o + 8, asz);
        cpa16(d + ARRB,       pAl + o,     asz);
        cpa16(d + ARRB + 16,  pAl + o + 8, asz);
        cpa16(d + 2*ARRB,     pBh + o,     16);
        cpa16(d + 2*ARRB+16,  pBh + o + 8, 16);
        cpa16(d + 3*ARRB,     pBl + o,     16);
        cpa16(d + 3*ARRB+16,  pBl + o + 8, 16);
        CPA_COMMIT();
    };

    issue(0, 0);

    for (int ch=0; ch<NCH; ch++){
        if (ch+1 < NCH){
            issue(ch+1, (ch+1)&1);
            CPA_WAIT1();
        } else {
            CPA_WAIT0();
        }
        __syncthreads();
        const uint32_t so = (uint32_t)(ch&1)*STGB2;
        #pragma unroll
        for (int k16=0;k16<2;k16++){
            const uint32_t ko = so + (uint32_t)k16*32;
            uint32_t af[4][4], bh[2][4], bl[2][4];
            #pragma unroll
            for (int i=0;i<4;i++)
                ldsm4(af[i][0],af[i][1],af[i][2],af[i][3], aAh + i*16*SKP*2 + ko);
            #pragma unroll
            for (int p=0;p<2;p++)
                ldsm4(bh[p][0],bh[p][1],bh[p][2],bh[p][3], aBh + p*16*SKP*2 + ko);
            #pragma unroll
            for (int p=0;p<2;p++)
                ldsm4(bl[p][0],bl[p][1],bl[p][2],bl[p][3], aBl + p*16*SKP*2 + ko);
            #pragma unroll
            for (int i=0;i<4;i++)
                #pragma unroll
                for (int j=0;j<4;j++)
                    mma16816(acc[i][j][0],acc[i][j][1],acc[i][j][2],acc[i][j][3],
                             af[i][0],af[i][1],af[i][2],af[i][3],
                             bh[j>>1][(j&1)*2], bh[j>>1][(j&1)*2+1]);
            #pragma unroll
            for (int i=0;i<4;i++)
                #pragma unroll
                for (int j=0;j<4;j++)
                    mma16816(acc[i][j][0],acc[i][j][1],acc[i][j][2],acc[i][j][3],
                             af[i][0],af[i][1],af[i][2],af[i][3],
                             bl[j>>1][(j&1)*2], bl[j>>1][(j&1)*2+1]);
            #pragma unroll
            for (int i=0;i<4;i++)
                ldsm4(af[i][0],af[i][1],af[i][2],af[i][3], aAl + i*16*SKP*2 + ko);
            #pragma unroll
            for (int i=0;i<4;i++)
                #pragma unroll
                for (int j=0;j<4;j++)
                    mma16816(acc[i][j][0],acc[i][j][1],acc[i][j][2],acc[i][j][3],
                             af[i][0],af[i][1],af[i][2],af[i][3],
                             bh[j>>1][(j&1)*2], bh[j>>1][(j&1)*2+1]);
        }
        __syncthreads();
    }

    // ---- epilogue (register accumulators) ----
    #pragma unroll
    for (int i=0;i<4;i++){
        #pragma unroll
        for (int j=0;j<4;j++){
            int m0 = row0 + warp_m*64 + i*16 + (lane>>2);
            int n0 = col0 + warp_n*32 + j*8 + (lane&3)*2;
            float bs0 = bias[n0], bs1 = bias[n0+1];
            #pragma unroll
            for (int half=0; half<2; half++){
                int m = m0 + half*8;
                if (m >= M) continue;
                float v0 = acc[i][j][half*2]   + bs0;
                float v1 = acc[i][j][half*2+1] + bs1;
                if (MODE == 1){
                    const float2 rv = *(const float2*)(resid + (size_t)m*Nc + n0);
                    v0 += rv.x; v1 += rv.y;
                }
                if (MODE == 2){
                    v0 = 0.5f*v0*(1.f + erff(v0*0.70710678118654752f));
                    v1 = 0.5f*v1*(1.f + erff(v1*0.70710678118654752f));
                    bf162 hv, lv;
                    f2pair(v0, hv.x, lv.x); f2pair(v1, hv.y, lv.y);
                    *(bf162*)(Ch + (size_t)m*Nc + n0) = hv;
                    *(bf162*)(Cl + (size_t)m*Nc + n0) = lv;
                } else if (MODE == 3){
                    if (z < 2){
                        if (z == 0){ v0 *= ATT_SCALE; v1 *= ATT_SCALE; }
                        bf16* Oh = (z==0)? Ch : Kh2;
                        bf16* Ol = (z==0)? Cl : Kl2;
                        bf162 hv, lv;
                        f2pair(v0, hv.x, lv.x); f2pair(v1, hv.y, lv.y);
                        *(bf162*)(Oh + (size_t)m*Nc + n0) = hv;
                        *(bf162*)(Ol + (size_t)m*Nc + n0) = lv;
                    } else {
                        int bq = m / NTOK, t = m - bq*NTOK;
                        size_t r0 = ((size_t)bq*DD + n0)*NTP + t;
                        bf16 h0,l0,h1,l1;
                        f2pair(v0,h0,l0); f2pair(v1,h1,l1);
                        VTh[r0] = h0;      VTl[r0] = l0;
                        VTh[r0+NTP] = h1;  VTl[r0+NTP] = l1;
                    }
                } else {
                    float2 ov; ov.x=v0; ov.y=v1;
                    *(float2*)(C + (size_t)m*Nc + n0) = ov;
                }
            }
        }
    }
}

// ======================================================================
// attention scores: S = (Q*scale) @ K^T  via split-bf16 mma.sync
// ======================================================================
#define SK2 72
__global__ void __launch_bounds__(128)
attn_scores_tc(const bf16* __restrict__ Qh, const bf16* __restrict__ Ql,
               const bf16* __restrict__ Kh, const bf16* __restrict__ Kl,
               float* __restrict__ S){
    __shared__ __align__(16) bf16 sQh[64*SK2], sQl[64*SK2], sKh[64*SK2], sKl[64*SK2];
    int bh = blockIdx.z, b = bh/NHD, h = bh%NHD;
    int i0 = blockIdx.y*64, j0 = blockIdx.x*64;
    int tid = threadIdx.x, wid = tid>>5, lane = tid&31;
    const uint4 zz = make_uint4(0,0,0,0);
    for (int l = tid; l < 512; l += 128){
        int r = l>>3, sg = (l&7)*8;
        int qi = i0 + r, kj = j0 + r;
        size_t qoff = ((size_t)(b*NTOK + qi))*DD + h*HDD + sg;
        size_t koff = ((size_t)(b*NTOK + kj))*DD + h*HDD + sg;
        uint4 vqh = (qi<NTOK)? *(const uint4*)(Qh+qoff) : zz;
        uint4 vql = (qi<NTOK)? *(const uint4*)(Ql+qoff) : zz;
        uint4 vkh = (kj<NTOK)? *(const uint4*)(Kh+koff) : zz;
        uint4 vkl = (kj<NTOK)? *(const uint4*)(Kl+koff) : zz;
        *(uint4*)(&sQh[r*SK2+sg]) = vqh;
        *(uint4*)(&sQl[r*SK2+sg]) = vql;
        *(uint4*)(&sKh[r*SK2+sg]) = vkh;
        *(uint4*)(&sKl[r*SK2+sg]) = vkl;
    }
    __syncthreads();
    int a_m = wid*16 + (lane&7) + ((lane>>3)&1)*8;
    int a_k = (lane>>4)*8;
    uint32_t aQh = smem_u32(sQh) + (uint32_t)(a_m*SK2 + a_k)*2;
    uint32_t aQl = smem_u32(sQl) + (uint32_t)(a_m*SK2 + a_k)*2;
    int b_n = (lane&7) + (lane>>4)*8;
    int b_k = ((lane>>3)&1)*8;
    uint32_t aKh = smem_u32(sKh) + (uint32_t)(b_n*SK2 + b_k)*2;
    uint32_t aKl = smem_u32(sKl) + (uint32_t)(b_n*SK2 + b_k)*2;

    float acc[8][4];
    #pragma unroll
    for (int j=0;j<8;j++)
        #pragma unroll
        for (int r=0;r<4;r++) acc[j][r]=0.f;

    #pragma unroll
    for (int k16=0;k16<4;k16++){
        uint32_t ko = (uint32_t)k16*32;
        uint32_t qh_[4], ql_[4], kh_[4][4], kl_[4][4];
        ldsm4(qh_[0],qh_[1],qh_[2],qh_[3], aQh + ko);
        ldsm4(ql_[0],ql_[1],ql_[2],ql_[3], aQl + ko);
        #pragma unroll
        for (int p=0;p<4;p++){
            ldsm4(kh_[p][0],kh_[p][1],kh_[p][2],kh_[p][3], aKh + (uint32_t)p*16*SK2*2 + ko);
            ldsm4(kl_[p][0],kl_[p][1],kl_[p][2],kl_[p][3], aKl + (uint32_t)p*16*SK2*2 + ko);
        }
        #pragma unroll
        for (int j=0;j<8;j++)
            mma16816(acc[j][0],acc[j][1],acc[j][2],acc[j][3],
                     qh_[0],qh_[1],qh_[2],qh_[3],
                     kh_[j>>1][(j&1)*2], kh_[j>>1][(j&1)*2+1]);
        #pragma unroll
        for (int j=0;j<8;j++)
            mma16816(acc[j][0],acc[j][1],acc[j][2],acc[j][3],
                     qh_[0],qh_[1],qh_[2],qh_[3],
                     kl_[j>>1][(j&1)*2], kl_[j>>1][(j&1)*2+1]);
        #pragma unroll
        for (int j=0;j<8;j++)
            mma16816(acc[j][0],acc[j][1],acc[j][2],acc[j][3],
                     ql_[0],ql_[1],ql_[2],ql_[3],
                     kh_[j>>1][(j&1)*2], kh_[j>>1][(j&1)*2+1]);
    }
    float* sp = S + (size_t)bh*NTP*NTP;
    #pragma unroll
    for (int j=0;j<8;j++){
        int n0 = j0 + j*8 + (lane&3)*2;
        #pragma unroll
        for (int half=0;half<2;half++){
            int m = i0 + wid*16 + (lane>>2) + half*8;
            if (m < NTOK){
                sp[(size_t)m*NTP + n0]   = acc[j][half*2];
                sp[(size_t)m*NTP + n0+1] = acc[j][half*2+1];
            }
        }
    }
}

// ---------------- softmax: S row -> P bf16 hi/lo (zero-padded to NTP) ----------------
__global__ void __launch_bounds__(256)
softmax_bf(const float* __restrict__ S, bf16* __restrict__ Ph, bf16* __restrict__ Pl){
    __shared__ float buf[NTP];
    __shared__ float sh[8];
    int bh = blockIdx.y, q = blockIdx.x;
    const float* r = S + ((size_t)bh*NTP + q)*NTP;
    int lane = threadIdx.x&31, wid = threadIdx.x>>5;
    float mx = -3.4e38f;
    for (int i=threadIdx.x;i<NTOK;i+=256){ float v=r[i]; buf[i]=v; mx=fmaxf(mx,v); }
    mx = warp_max(mx);
    if (lane==0) sh[wid]=mx;
    __syncthreads();
    if (wid==0){
        float a = (lane<8)? sh[lane] : -3.4e38f;
        a = warp_max(a);
        if (lane==0) sh[0]=a;
    }
    __syncthreads();
    float M = sh[0];
    __syncthreads();
    float s = 0.f;
    for (int i=threadIdx.x;i<NTOK;i+=256){ float e = expf(buf[i]-M); buf[i]=e; s+=e; }
    s = warp_sum(s);
    if (lane==0) sh[wid]=s;
    __syncthreads();
    if (wid==0){
        float a = (lane<8)? sh[lane] : 0.f;
        a = warp_sum(a);
        if (lane==0) sh[0]=a;
    }
    __syncthreads();
    float inv = 1.f/sh[0];
    bf162* ph2 = (bf162*)(Ph + ((size_t)bh*NTP + q)*NTP);
    bf162* pl2 = (bf162*)(Pl + ((size_t)bh*NTP + q)*NTP);
    for (int i=threadIdx.x;i<NTP/2;i+=256){
        int j0 = i*2;
        float v0 = (j0   < NTOK)? buf[j0]*inv   : 0.f;
        float v1 = (j0+1 < NTOK)? buf[j0+1]*inv : 0.f;
        bf162 hv, lv;
        f2pair(v0, hv.x, lv.x); f2pair(v1, hv.y, lv.y);
        ph2[i]=hv; pl2[i]=lv;
    }
}

// ======================================================================
// attention AV: O = P @ V  via split-bf16 mma.sync
// ======================================================================
__global__ void __launch_bounds__(128)
attn_av_tc(const bf16* __restrict__ Ph, const bf16* __restrict__ Pl,
           const bf16* __restrict__ VTh, const bf16* __restrict__ VTl,
           bf16* __restrict__ Oh, bf16* __restrict__ Ol){
    __shared__ __align__(16) bf16 sPh[64*SK2], sPl[64*SK2], sVh[64*SK2], sVl[64*SK2];
    int bh = blockIdx.y, b = bh/NHD, h = bh%NHD;
    int i0 = blockIdx.x*64;
    int tid = threadIdx.x, wid = tid>>5, lane = tid&31;

    int a_m = wid*16 + (lane&7) + ((lane>>3)&1)*8;
    int a_k = (lane>>4)*8;
    uint32_t aPh = smem_u32(sPh) + (uint32_t)(a_m*SK2 + a_k)*2;
    uint32_t aPl = smem_u32(sPl) + (uint32_t)(a_m*SK2 + a_k)*2;
    int b_n = (lane&7) + (lane>>4)*8;
    int b_k = ((lane>>3)&1)*8;
    uint32_t aVh = smem_u32(sVh) + (uint32_t)(b_n*SK2 + b_k)*2;
    uint32_t aVl = smem_u32(sVl) + (uint32_t)(b_n*SK2 + b_k)*2;

    float acc[8][4];
    #pragma unroll
    for (int j=0;j<8;j++)
        #pragma unroll
        for (int r=0;r<4;r++) acc[j][r]=0.f;

    for (int chk=0; chk<NTP/64; chk++){
        for (int l = tid; l < 512; l += 128){
            int r = l>>3, sg = (l&7)*8;
            size_t poff = ((size_t)bh*NTP + i0 + r)*NTP + chk*64 + sg;
            size_t voff = ((size_t)b*DD + h*HDD + r)*NTP + chk*64 + sg;
            *(uint4*)(&sPh[r*SK2+sg]) = *(const uint4*)(Ph+poff);
            *(uint4*)(&sPl[r*SK2+sg]) = *(const uint4*)(Pl+poff);
            *(uint4*)(&sVh[r*SK2+sg]) = *(const uint4*)(VTh+voff);
            *(uint4*)(&sVl[r*SK2+sg]) = *(const uint4*)(VTl+voff);
        }
        __syncthreads();
        #pragma unroll
        for (int k16=0;k16<4;k16++){
            uint32_t ko = (uint32_t)k16*32;
            uint32_t ph_[4], pl_[4], vh_[4][4], vl_[4][4];
            ldsm4(ph_[0],ph_[1],ph_[2],ph_[3], aPh + ko);
            ldsm4(pl_[0],pl_[1],pl_[2],pl_[3], aPl + ko);
            #pragma unroll
            for (int p=0;p<4;p++){
                ldsm4(vh_[p][0],vh_[p][1],vh_[p][2],vh_[p][3], aVh + (uint32_t)p*16*SK2*2 + ko);
                ldsm4(vl_[p][0],vl_[p][1],vl_[p][2],vl_[p][3], aVl + (uint32_t)p*16*SK2*2 + ko);
            }
            #pragma unroll
            for (int j=0;j<8;j++)
                mma16816(acc[j][0],acc[j][1],acc[j][2],acc[j][3],
                         ph_[0],ph_[1],ph_[2],ph_[3],
                         vh_[j>>1][(j&1)*2], vh_[j>>1][(j&1)*2+1]);
            #pragma unroll
            for (int j=0;j<8;j++)
                mma16816(acc[j][0],acc[j][1],acc[j][2],acc[j][3],
                         ph_[0],ph_[1],ph_[2],ph_[3],
                         vl_[j>>1][(j&1)*2], vl_[j>>1][(j&1)*2+1]);
            #pragma unroll
            for (int j=0;j<8;j++)
                mma16816(acc[j][0],acc[j][1],acc[j][2],acc[j][3],
                         pl_[0],pl_[1],pl_[2],pl_[3],
                         vh_[j>>1][(j&1)*2], vh_[j>>1][(j&1)*2+1]);
        }
        __syncthreads();
    }
    #pragma unroll
    for (int j=0;j<8;j++){
        int n0 = h*HDD + j*8 + (lane&3)*2;
        #pragma unroll
        for (int half=0;half<2;half++){
            int m = i0 + wid*16 + (lane>>2) + half*8;
            if (m < NTOK){
                bf162 hv, lv;
                f2pair(acc[j][half*2],   hv.x, lv.x);
                f2pair(acc[j][half*2+1], hv.y, lv.y);
                size_t o = ((size_t)(b*NTOK + m))*DD + n0;
                *(bf162*)(Oh + o) = hv;
                *(bf162*)(Ol + o) = lv;
            }
        }
    }
}

// ---------------- SIMT gemm for the tiny head GEMM ----------------
__global__ void __launch_bounds__(256)
gemm128(const float* __restrict__ A, const float* __restrict__ Wt,
        const float* __restrict__ bias, float* __restrict__ Cc,
        int M, int Nc, int K){
    __shared__ __align__(16) float As[8][132];
    __shared__ __align__(16) float Bs[8][128];
    int tid = threadIdx.x;
    int tx = tid & 15, ty = tid >> 4;
    int row0 = blockIdx.y * 128, col0 = blockIdx.x * 128;
    float acc[8][8];
    #pragma unroll
    for (int i=0;i<8;i++)
        #pragma unroll
        for (int j=0;j<8;j++) acc[i][j]=0.f;
    for (int k0=0;k0<K;k0+=8){
        #pragma unroll
        for (int t=0;t<4;t++){
            int lin = tid*4+t;
            int r = lin>>3, c = lin&7;
            int gr = row0+r;
            As[c][r] = (gr<M) ? A[(size_t)gr*K + k0 + c] : 0.f;
        }
        #pragma unroll
        for (int t=0;t<4;t++){
            int lin = tid*4+t;
            int r = lin>>7, c = lin&127;
            int gc = col0+c;
            Bs[r][c] = (gc<Nc) ? Wt[(size_t)(k0+r)*Nc + gc] : 0.f;
        }
        __syncthreads();
        #pragma unroll
        for (int k=0;k<8;k++){
            float av[8], bv[8];
            #pragma unroll
            for (int i=0;i<8;i++) av[i]=As[k][ty*8+i];
            #pragma unroll
            for (int j=0;j<8;j++) bv[j]=Bs[k][tx*8+j];
            #pragma unroll
            for (int i=0;i<8;i++)
                #pragma unroll
                for (int j=0;j<8;j++)
                    acc[i][j] = fmaf(av[i], bv[j], acc[i][j]);
        }
        __syncthreads();
    }
    #pragma unroll
    for (int i=0;i<8;i++){
        int gr = row0 + ty*8 + i;
        if (gr>=M) continue;
        #pragma unroll
        for (int j=0;j<8;j++){
            int gc = col0 + tx*8 + j;
            if (gc>=Nc) continue;
            Cc[(size_t)gr*Nc + gc] = acc[i][j] + bias[gc];
        }
    }
}

// ---------------- host driver ----------------
extern "C" void kernel_launch(void* const* d_in, const int* in_sizes, int n_in,
                              void* d_out, int out_size){
    const float* x      = (const float*)d_in[0];
    const float* proj_w = (const float*)d_in[1];
    const float* proj_b = (const float*)d_in[2];
    const float* cls    = (const float*)d_in[3];
    const float* pos    = (const float*)d_in[4];
    const float* ln1_g  = (const float*)d_in[5];
    const float* ln1_b  = (const float*)d_in[6];
    const float* qw = (const float*)d_in[7];  const float* qb = (const float*)d_in[8];
    const float* kw = (const float*)d_in[9];  const float* kb = (const float*)d_in[10];
    const float* vw = (const float*)d_in[11]; const float* vb = (const float*)d_in[12];
    const float* ow = (const float*)d_in[13]; const float* ob = (const float*)d_in[14];
    const float* ln2_g = (const float*)d_in[15]; const float* ln2_b = (const float*)d_in[16];
    const float* fcw = (const float*)d_in[17]; const float* fcb = (const float*)d_in[18];
    const float* pw  = (const float*)d_in[19]; const float* pb  = (const float*)d_in[20];
    const float* lnf_g = (const float*)d_in[21]; const float* lnf_b = (const float*)d_in[22];
    const float* head_w = (const float*)d_in[23]; const float* head_b = (const float*)d_in[24];
    float* out = (float*)d_out;

    float *emb_, *h_, *S_, *cls_;
    bf16 *th_, *tl_, *yh_, *yl_, *qh_, *ql_, *kh_, *kl_, *vth_, *vtl_;
    bf16 *ph_, *pl_, *aoh_, *aol_, *mh_, *ml_;
    bf16 *wqkvTh_, *wqkvTl_, *woTh_, *woTl_, *wfcTh_, *wfcTl_, *wpwTh_, *wpwTl_, *wprojTh_, *wprojTl_;
    cudaGetSymbolAddress((void**)&emb_,g_emb);
    cudaGetSymbolAddress((void**)&h_,  g_h);
    cudaGetSymbolAddress((void**)&S_,  g_S);
    cudaGetSymbolAddress((void**)&cls_,g_cls);
    cudaGetSymbolAddress((void**)&th_, g_th);
    cudaGetSymbolAddress((void**)&tl_, g_tl);
    cudaGetSymbolAddress((void**)&yh_, g_yh);
    cudaGetSymbolAddress((void**)&yl_, g_yl);
    cudaGetSymbolAddress((void**)&qh_, g_qh);
    cudaGetSymbolAddress((void**)&ql_, g_ql);
    cudaGetSymbolAddress((void**)&kh_, g_kh);
    cudaGetSymbolAddress((void**)&kl_, g_kl);
    cudaGetSymbolAddress((void**)&vth_,g_vth);
    cudaGetSymbolAddress((void**)&vtl_,g_vtl);
    cudaGetSymbolAddress((void**)&ph_, g_ph);
    cudaGetSymbolAddress((void**)&pl_, g_pl);
    cudaGetSymbolAddress((void**)&aoh_,g_aoh);
    cudaGetSymbolAddress((void**)&aol_,g_aol);
    cudaGetSymbolAddress((void**)&mh_, g_mh);
    cudaGetSymbolAddress((void**)&ml_, g_ml);
    cudaGetSymbolAddress((void**)&wqkvTh_, g_wqkvTh);
    cudaGetSymbolAddress((void**)&wqkvTl_, g_wqkvTl);
    cudaGetSymbolAddress((void**)&woTh_,   g_woTh);
    cudaGetSymbolAddress((void**)&woTl_,   g_woTl);
    cudaGetSymbolAddress((void**)&wfcTh_,  g_wfcTh);
    cudaGetSymbolAddress((void**)&wfcTl_,  g_wfcTl);
    cudaGetSymbolAddress((void**)&wpwTh_,  g_wpwTh);
    cudaGetSymbolAddress((void**)&wpwTl_,  g_wpwTl);
    cudaGetSymbolAddress((void**)&wprojTh_,g_wprojTh);
    cudaGetSymbolAddress((void**)&wprojTl_,g_wprojTl);

    cudaFuncSetAttribute(gemm_tc<0>, cudaFuncAttributeMaxDynamicSharedMemorySize, GT_DSMEM);
    cudaFuncSetAttribute(gemm_tc<1>, cudaFuncAttributeMaxDynamicSharedMemorySize, GT_DSMEM);
    cudaFuncSetAttribute(gemm_tc<2>, cudaFuncAttributeMaxDynamicSharedMemorySize, GT_DSMEM);
    cudaFuncSetAttribute(gemm_tc<3>, cudaFuncAttributeMaxDynamicSharedMemorySize, GT_DSMEM);

    // ---- weight transposes + bf16 hi/lo conversion ----
    dim3 tb(32,8);
    transpose_bf<<<dim3(24,24,NLAYER),tb>>>(qw, (size_t)DD*DD, wqkvTh_ + 0*(size_t)DD*DD, wqkvTl_ + 0*(size_t)DD*DD, (size_t)3*DD*DD, DD, DD);
    transpose_bf<<<dim3(24,24,NLAYER),tb>>>(kw, (size_t)DD*DD, wqkvTh_ + 1*(size_t)DD*DD, wqkvTl_ + 1*(size_t)DD*DD, (size_t)3*DD*DD, DD, DD);
    transpose_bf<<<dim3(24,24,NLAYER),tb>>>(vw, (size_t)DD*DD, wqkvTh_ + 2*(size_t)DD*DD, wqkvTl_ + 2*(size_t)DD*DD, (size_t)3*DD*DD, DD, DD);
    transpose_bf<<<dim3(24,24,NLAYER),tb>>>(ow, (size_t)DD*DD, woTh_, woTl_, (size_t)DD*DD, DD, DD);
    transpose_bf<<<dim3(96,24,NLAYER),tb>>>(fcw,(size_t)DD*MLPD, wfcTh_, wfcTl_, (size_t)MLPD*DD, DD, MLPD);
    transpose_bf<<<dim3(24,96,NLAYER),tb>>>(pw, (size_t)MLPD*DD, wpwTh_, wpwTl_, (size_t)DD*MLPD, MLPD, DD);
    transpose_bf<<<dim3(24,24,1),tb>>>(proj_w, 0, wprojTh_, wprojTl_, 0, DD, DD);
    zero_vt_pad<<<512,256>>>(vth_, vtl_);

    // ---- patch embed ----
    patch_gather<<<2048, 256>>>(x, th_, tl_);
    gemm_tc<0><<<dim3(6,36,1),256,GT_DSMEM>>>(th_, tl_, wprojTh_, wprojTl_,
                                     proj_b,proj_b,proj_b, nullptr,
                                     emb_,emb_,emb_, nullptr,nullptr,
                                     nullptr,nullptr,nullptr,nullptr, PROWS, DD, DD);
    assemble<<<2048, 256>>>(emb_, cls, pos, h_);

    dim3 gD(6,37,1), gQKV(6,37,3), gFC(24,37,1);
    dim3 gSc(NTP/64, NTP/64, BSZ*NHD);
    dim3 gSm(NTOK, BSZ*NHD);
    dim3 gAv(NTP/64, BSZ*NHD);

    for (int l=0; l<NLAYER; l++){
        layernorm_bf<<<ROWS,256>>>(h_, ln1_g+l*DD, ln1_b+l*DD, yh_, yl_, ROWS);
        gemm_tc<3><<<gQKV,256,GT_DSMEM>>>(yh_, yl_,
                                 wqkvTh_ + (size_t)l*3*DD*DD, wqkvTl_ + (size_t)l*3*DD*DD,
                                 qb+l*DD, kb+l*DD, vb+l*DD, nullptr,
                                 nullptr,nullptr,nullptr,
                                 qh_, ql_, kh_, kl_, vth_, vtl_, ROWS, DD, DD);
        attn_scores_tc<<<gSc,128>>>(qh_, ql_, kh_, kl_, S_);
        softmax_bf<<<gSm,256>>>(S_, ph_, pl_);
        attn_av_tc<<<gAv,128>>>(ph_, pl_, vth_, vtl_, aoh_, aol_);
        gemm_tc<1><<<gD,256,GT_DSMEM>>>(aoh_, aol_,
                               woTh_ + (size_t)l*DD*DD, woTl_ + (size_t)l*DD*DD,
                               ob+l*DD, ob+l*DD, ob+l*DD, h_,
                               h_, h_, h_, nullptr,nullptr,
                               nullptr,nullptr,nullptr,nullptr, ROWS, DD, DD);
        layernorm_bf<<<ROWS,256>>>(h_, ln2_g+l*DD, ln2_b+l*DD, yh_, yl_, ROWS);
        gemm_tc<2><<<gFC,256,GT_DSMEM>>>(yh_, yl_,
                                wfcTh_ + (size_t)l*MLPD*DD, wfcTl_ + (size_t)l*MLPD*DD,
                                fcb+l*MLPD, fcb+l*MLPD, fcb+l*MLPD, nullptr,
                                nullptr,nullptr,nullptr, mh_, ml_,
                                nullptr,nullptr,nullptr,nullptr, ROWS, MLPD, DD);
        gemm_tc<1><<<gD,256,GT_DSMEM>>>(mh_, ml_,
                               wpwTh_ + (size_t)l*DD*MLPD, wpwTl_ + (size_t)l*DD*MLPD,
                               pb+l*DD, pb+l*DD, pb+l*DD, h_,
                               h_, h_, h_, nullptr,nullptr,
                               nullptr,nullptr,nullptr,nullptr, ROWS, DD, MLPD);
    }

    layernorm_f<<<BSZ,256>>>(h_, (size_t)NTOK*DD, lnf_g, lnf_b, cls_, BSZ);
    gemm128<<<dim3((NCLS+127)/128,1),256>>>(cls_, head_w, head_b, out, BSZ, NCLS, DD);
}